// round 4
// baseline (speedup 1.0000x reference)
#include <cuda_runtime.h>
#include <cuda_bf16.h>
#include <cstdint>

#define I_DIM 2048
#define H_DIM 96
#define B_DIM 64
#define T_DIM 512

typedef unsigned long long ull;

// ============================ generic helpers ==============================

__device__ __forceinline__ void fma2(ull &d, ull a, ull b) {
    asm("fma.rn.f32x2 %0, %1, %2, %0;" : "+l"(d) : "l"(a), "l"(b));
}
__device__ __forceinline__ ull pack2(float lo, float hi) {
    ull v; asm("mov.b64 %0, {%1, %2};" : "=l"(v) : "f"(lo), "f"(hi)); return v;
}
// branch-free tanh: 1 - 2/(e^{2x}+1)
__device__ __forceinline__ float fast_tanh(float x) {
    float e = __expf(2.0f * x);
    return 1.0f - __fdividef(2.0f, e + 1.0f);
}
__device__ __forceinline__ uint32_t smem_u32(const void* p) {
    uint32_t a;
    asm("{ .reg .u64 t; cvta.to.shared.u64 t, %1; cvt.u32.u64 %0, t; }" : "=r"(a) : "l"(p));
    return a;
}
__device__ __forceinline__ void lds_v2u64(ull &x, ull &y, uint32_t a) {
    asm volatile("ld.shared.v2.b64 {%0,%1}, [%2];" : "=l"(x), "=l"(y) : "r"(a));
}
__device__ __forceinline__ void sts_f32(uint32_t a, float v) {
    asm volatile("st.shared.f32 [%0], %1;" :: "r"(a), "f"(v) : "memory");
}
__device__ __forceinline__ float lds_f32(uint32_t a) {
    float v; asm volatile("ld.shared.f32 %0, [%1];" : "=f"(v) : "r"(a)); return v;
}
__device__ __forceinline__ float hsum4(ull a0, ull a1) {
    ull t; asm("add.rn.f32x2 %0, %1, %2;" : "=l"(t) : "l"(a0), "l"(a1));
    float lo, hi; asm("mov.b64 {%0,%1}, %2;" : "=f"(lo), "=f"(hi) : "l"(t));
    return lo + hi;
}
#define BARRIER() asm volatile("bar.sync 0;" ::: "memory")

// ======================= mma.sync / ldmatrix helpers =======================

__device__ __forceinline__ void ldsm_x4(uint32_t &r0, uint32_t &r1, uint32_t &r2,
                                        uint32_t &r3, uint32_t addr) {
    asm volatile("ldmatrix.sync.aligned.m8n8.x4.shared.b16 {%0,%1,%2,%3}, [%4];"
                 : "=r"(r0), "=r"(r1), "=r"(r2), "=r"(r3) : "r"(addr));
}
__device__ __forceinline__ void mma16816(float* c, const uint32_t* a, const uint32_t* b) {
    asm volatile("mma.sync.aligned.m16n8k16.row.col.f32.bf16.bf16.f32 "
                 "{%0,%1,%2,%3}, {%4,%5,%6,%7}, {%8,%9}, {%0,%1,%2,%3};"
                 : "+f"(c[0]), "+f"(c[1]), "+f"(c[2]), "+f"(c[3])
                 : "r"(a[0]), "r"(a[1]), "r"(a[2]), "r"(a[3]), "r"(b[0]), "r"(b[1]));
}
__device__ __forceinline__ void cvt_hilo(float4 v, uint2 &hp, uint2 &lp) {
    __nv_bfloat162 h0 = __float22bfloat162_rn(make_float2(v.x, v.y));
    __nv_bfloat162 h1 = __float22bfloat162_rn(make_float2(v.z, v.w));
    float2 f0 = __bfloat1622float2(h0), f1 = __bfloat1622float2(h1);
    __nv_bfloat162 l0 = __float22bfloat162_rn(make_float2(v.x - f0.x, v.y - f0.y));
    __nv_bfloat162 l1 = __float22bfloat162_rn(make_float2(v.z - f1.x, v.w - f1.y));
    hp = make_uint2(*(uint32_t*)&h0, *(uint32_t*)&h1);
    lp = make_uint2(*(uint32_t*)&l0, *(uint32_t*)&l1);
}

// Scratch: layer-0 input projection, [B*T, 96]
__device__ float g_xproj[(size_t)B_DIM * T_DIM * H_DIM];

// ===========================================================================
// Kernel 1: xproj = x @ w_ih0^T + b_ih0, HMMA bf16 3-split. (unchanged, ~65us)
// ===========================================================================
#define ROWB 80
#define SM_BIAS 0
#define SM_AHI  512
#define SM_ALO  (512 + 20480)
#define SM_BHI  (512 + 40960)
#define SM_BLO  (512 + 40960 + 7680)
#define GEMM_SMEM (512 + 40960 + 15360)   // 56832 bytes

__global__ __launch_bounds__(256, 1) void xproj_gemm(const float* __restrict__ X,
                                                     const float* __restrict__ W,
                                                     const float* __restrict__ bias)
{
    extern __shared__ char smem[];
    float* sbias = (float*)(smem + SM_BIAS);
    const int tid = threadIdx.x, lane = tid & 31, warp = tid >> 5;
    const int rowbase = blockIdx.x * 256;
    const int m_warp = (warp & 3) * 64;
    const int n_warp = (warp >> 2) * 48;

    if (tid < H_DIM) sbias[tid] = __ldg(bias + tid);

    const int g = lane >> 3, r = lane & 7;
    const uint32_t lane_off = (uint32_t)((((g & 1) << 3) + r) * ROWB + ((g >> 1) << 4));
    const uint32_t sb = smem_u32(smem);
    const uint32_t aHiB = sb + SM_AHI + (uint32_t)m_warp * ROWB + lane_off;
    const uint32_t aLoB = sb + SM_ALO + (uint32_t)m_warp * ROWB + lane_off;
    const uint32_t bHiB = sb + SM_BHI + (uint32_t)n_warp * ROWB + lane_off;
    const uint32_t bLoB = sb + SM_BLO + (uint32_t)n_warp * ROWB + lane_off;

    float acc[4][6][4];
    #pragma unroll
    for (int mt = 0; mt < 4; mt++)
        #pragma unroll
        for (int nt = 0; nt < 6; nt++)
            #pragma unroll
            for (int i = 0; i < 4; i++) acc[mt][nt][i] = 0.f;

    float4 sa[8], sw[3];

    auto load_stage = [&](int k0) {
        #pragma unroll
        for (int it = 0; it < 8; ++it) {
            int f = tid + it * 256;
            sa[it] = *(const float4*)(X + (size_t)(rowbase + (f >> 3)) * I_DIM + k0 + ((f & 7) << 2));
        }
        #pragma unroll
        for (int it = 0; it < 3; ++it) {
            int f = tid + it * 256;
            sw[it] = *(const float4*)(W + (size_t)(f >> 3) * I_DIM + k0 + ((f & 7) << 2));
        }
    };
    auto store_stage = [&]() {
        #pragma unroll
        for (int it = 0; it < 8; ++it) {
            int f = tid + it * 256;
            int off = (f >> 3) * ROWB + ((f & 7) << 3);
            uint2 hp, lp; cvt_hilo(sa[it], hp, lp);
            *(uint2*)(smem + SM_AHI + off) = hp;
            *(uint2*)(smem + SM_ALO + off) = lp;
        }
        #pragma unroll
        for (int it = 0; it < 3; ++it) {
            int f = tid + it * 256;
            int off = (f >> 3) * ROWB + ((f & 7) << 3);
            uint2 hp, lp; cvt_hilo(sw[it], hp, lp);
            *(uint2*)(smem + SM_BHI + off) = hp;
            *(uint2*)(smem + SM_BLO + off) = lp;
        }
    };

    load_stage(0);
    store_stage();
    __syncthreads();

    const int NC = I_DIM / 32;   // 64
    for (int c = 0; c < NC; ++c) {
        if (c + 1 < NC) load_stage((c + 1) * 32);

        #pragma unroll
        for (int s = 0; s < 2; ++s) {
            uint32_t ah[4][4], al[4][4], bh[6][2], bl[6][2];
            #pragma unroll
            for (int mt = 0; mt < 4; ++mt) {
                ldsm_x4(ah[mt][0], ah[mt][1], ah[mt][2], ah[mt][3], aHiB + mt * (16 * ROWB) + s * 32);
                ldsm_x4(al[mt][0], al[mt][1], al[mt][2], al[mt][3], aLoB + mt * (16 * ROWB) + s * 32);
            }
            #pragma unroll
            for (int np = 0; np < 3; ++np) {
                uint32_t r0, r1, r2, r3;
                ldsm_x4(r0, r1, r2, r3, bHiB + np * (16 * ROWB) + s * 32);
                bh[2 * np][0] = r0; bh[2 * np + 1][0] = r1;
                bh[2 * np][1] = r2; bh[2 * np + 1][1] = r3;
                ldsm_x4(r0, r1, r2, r3, bLoB + np * (16 * ROWB) + s * 32);
                bl[2 * np][0] = r0; bl[2 * np + 1][0] = r1;
                bl[2 * np][1] = r2; bl[2 * np + 1][1] = r3;
            }
            #pragma unroll
            for (int mt = 0; mt < 4; ++mt)
                #pragma unroll
                for (int nt = 0; nt < 6; ++nt) {
                    mma16816(acc[mt][nt], ah[mt], bh[nt]);
                    mma16816(acc[mt][nt], ah[mt], bl[nt]);
                    mma16816(acc[mt][nt], al[mt], bh[nt]);
                }
        }
        __syncthreads();
        if (c + 1 < NC) { store_stage(); }
        __syncthreads();
    }

    #pragma unroll
    for (int nt = 0; nt < 6; ++nt) {
        int col = n_warp + nt * 8 + (lane & 3) * 2;
        float b0 = sbias[col], b1 = sbias[col + 1];
        #pragma unroll
        for (int mt = 0; mt < 4; ++mt) {
            int row0 = rowbase + m_warp + mt * 16 + (lane >> 2);
            float2 v0 = make_float2(acc[mt][nt][0] + b0, acc[mt][nt][1] + b1);
            float2 v1 = make_float2(acc[mt][nt][2] + b0, acc[mt][nt][3] + b1);
            *(float2*)(g_xproj + (size_t)row0 * H_DIM + col) = v0;
            *(float2*)(g_xproj + (size_t)(row0 + 8) * H_DIM + col) = v1;
        }
    }
}

// ===========================================================================
// Kernel 2: recurrent scan, 1 CTA / batch, 3-layer wavefront, 1 barrier/tick.
// 960 threads = 30 warps; every thread holds 48 weight floats (24 x f32x2)
// so nothing spills at the 68-reg budget.
//   warps  0-5  : layer0.  j = w*16+(lane&15), half = lane>>4 (K-split of whh0
//                 row). combine shfl_xor(16); lanes<16 finalize (xp + tanh).
//   warps  6-17 : layer1.  j = (w-6)*8+(lane&7), c = lane>>3:
//                 c0/c1 = wih1 row halves (reads h0 prev), c2/c3 = whh1 halves
//                 (reads h1 own). combine shfl_xor(8)+shfl_xor(16); lanes<8.
//   warps 18-29 : layer2 (same, reading h1 / h2).
// h state: hs[6][104] (104-float rows -> the 4 distinct 16B segments a warp
// loads land on disjoint bank groups). Parity double-buffering by time step.
// ===========================================================================
#define ROWF 104
#define ROWBYTES (ROWF * 4)

__global__ __launch_bounds__(960, 1) void rnn_scan(
    const float* __restrict__ whh0, const float* __restrict__ bhh0,
    const float* __restrict__ wih1, const float* __restrict__ whh1,
    const float* __restrict__ bih1, const float* __restrict__ bhh1,
    const float* __restrict__ wih2, const float* __restrict__ whh2,
    const float* __restrict__ bih2, const float* __restrict__ bhh2,
    const float* __restrict__ fcw,  const float* __restrict__ fcb,
    float* __restrict__ out)
{
    // rows: 0,1 = h0 parity 0/1 ; 2,3 = h1 ; 4,5 = h2
    __shared__ __align__(16) float hs[6][ROWF];
    __shared__ float sred[96];

    const int tid = threadIdx.x, lane = tid & 31, warp = tid >> 5;
    const int b = blockIdx.x;

    for (int i = tid; i < 6 * ROWF; i += 960) ((float*)hs)[i] = 0.f;

    const uint32_t sbase = smem_u32(&hs[0][0]);
    #define HADDR(arr, off) (sbase + (uint32_t)((arr) * ROWBYTES + (off) * 4))

    ull w[24];
    uint32_t srcA0, srcA1, dst0, dst1;   // src/dst smem addr for parity 0 / 1
    float bias = 0.f;
    bool writer;
    int role, j;
    const float* wr;

    if (warp < 6) {
        role = 0;
        j = warp * 16 + (lane & 15);
        int seg = (lane >> 4) * 48;
        srcA0 = HADDR(1, seg);  srcA1 = HADDR(0, seg);   // h0[q], q = 1-p
        dst0  = HADDR(0, j);    dst1  = HADDR(1, j);     // h0[p]
        wr = whh0 + j * 96 + seg;
        writer = (lane < 16);
        if (writer) bias = __ldg(bhh0 + j);
    } else if (warp < 18) {
        role = 1;
        j = (warp - 6) * 8 + (lane & 7);
        int c = lane >> 3;
        int seg = (c & 1) * 48;
        if (c < 2) { srcA0 = HADDR(1, seg); srcA1 = HADDR(0, seg); }  // h0[q]
        else       { srcA0 = HADDR(2, seg); srcA1 = HADDR(3, seg); }  // h1[p]
        dst0 = HADDR(3, j);  dst1 = HADDR(2, j);                       // h1[q]
        wr = ((c < 2) ? wih1 : whh1) + j * 96 + seg;
        writer = (lane < 8);
        if (writer) bias = __ldg(bih1 + j) + __ldg(bhh1 + j);
    } else {
        role = 2;
        j = (warp - 18) * 8 + (lane & 7);
        int c = lane >> 3;
        int seg = (c & 1) * 48;
        if (c < 2) { srcA0 = HADDR(2, seg); srcA1 = HADDR(3, seg); }  // h1[p]
        else       { srcA0 = HADDR(5, seg); srcA1 = HADDR(4, seg); }  // h2[q]
        dst0 = HADDR(4, j);  dst1 = HADDR(5, j);                       // h2[p]
        wr = ((c < 2) ? wih2 : whh2) + j * 96 + seg;
        writer = (lane < 8);
        if (writer) bias = __ldg(bih2 + j) + __ldg(bhh2 + j);
    }

    #pragma unroll
    for (int qq = 0; qq < 24; qq++)
        w[qq] = pack2(__ldg(wr + 2 * qq), __ldg(wr + 2 * qq + 1));

    const float* xpp = g_xproj + ((size_t)b * T_DIM) * H_DIM + j;
    float xp = (role == 0 && writer) ? __ldg(xpp) : 0.f;

    BARRIER();

    if (role == 0) {
        for (int u = 0; u < T_DIM + 2; ++u) {
            const int p = u & 1;
            if (u < T_DIM) {
                uint32_t src = p ? srcA1 : srcA0;
                ull a0 = 0, a1 = 0;
                #pragma unroll
                for (int m = 0; m < 12; m++) {
                    ull vx, vy; lds_v2u64(vx, vy, src + 16 * m);
                    fma2(a0, w[2 * m], vx);
                    fma2(a1, w[2 * m + 1], vy);
                }
                float s = hsum4(a0, a1);
                s += __shfl_xor_sync(0xffffffffu, s, 16);
                if (writer) {
                    sts_f32(p ? dst1 : dst0, fast_tanh(s + xp + bias));
                    if (u + 1 < T_DIM) xp = __ldg(xpp + (u + 1) * H_DIM);
                }
            }
            BARRIER();
        }
    } else if (role == 1) {
        for (int u = 0; u < T_DIM + 2; ++u) {
            const int p = u & 1;
            if (u >= 1 && u <= T_DIM) {
                uint32_t src = p ? srcA1 : srcA0;
                ull a0 = 0, a1 = 0;
                #pragma unroll
                for (int m = 0; m < 12; m++) {
                    ull vx, vy; lds_v2u64(vx, vy, src + 16 * m);
                    fma2(a0, w[2 * m], vx);
                    fma2(a1, w[2 * m + 1], vy);
                }
                float s = hsum4(a0, a1);
                s += __shfl_xor_sync(0xffffffffu, s, 8);
                s += __shfl_xor_sync(0xffffffffu, s, 16);
                if (writer) sts_f32(p ? dst1 : dst0, fast_tanh(s + bias));
            }
            BARRIER();
        }
    } else {
        for (int u = 0; u < T_DIM + 2; ++u) {
            const int p = u & 1;
            if (u >= 2 && u <= T_DIM + 1) {
                uint32_t src = p ? srcA1 : srcA0;
                ull a0 = 0, a1 = 0;
                #pragma unroll
                for (int m = 0; m < 12; m++) {
                    ull vx, vy; lds_v2u64(vx, vy, src + 16 * m);
                    fma2(a0, w[2 * m], vx);
                    fma2(a1, w[2 * m + 1], vy);
                }
                float s = hsum4(a0, a1);
                s += __shfl_xor_sync(0xffffffffu, s, 8);
                s += __shfl_xor_sync(0xffffffffu, s, 16);
                if (writer) sts_f32(p ? dst1 : dst0, fast_tanh(s + bias));
            }
            BARRIER();
        }
    }

    // FC head: out[b] = h2(T-1) . fc_w + fc_b. h2(511) written at u=513 (p=1)
    // -> row 5.
    if (tid < 96) sred[tid] = lds_f32(HADDR(5, tid)) * __ldg(fcw + tid);
    BARRIER();
    if (tid == 0) {
        float s = __ldg(fcb);
        #pragma unroll
        for (int k = 0; k < 96; k++) s += sred[k];
        out[b] = s;
    }
    #undef HADDR
}

extern "C" void kernel_launch(void* const* d_in, const int* in_sizes, int n_in,
                              void* d_out, int out_size) {
    const float* x     = (const float*)d_in[0];
    const float* w_ih0 = (const float*)d_in[1];
    const float* w_hh0 = (const float*)d_in[2];
    const float* b_ih0 = (const float*)d_in[3];
    const float* b_hh0 = (const float*)d_in[4];
    const float* w_ih1 = (const float*)d_in[5];
    const float* w_hh1 = (const float*)d_in[6];
    const float* b_ih1 = (const float*)d_in[7];
    const float* b_hh1 = (const float*)d_in[8];
    const float* w_ih2 = (const float*)d_in[9];
    const float* w_hh2 = (const float*)d_in[10];
    const float* b_ih2 = (const float*)d_in[11];
    const float* b_hh2 = (const float*)d_in[12];
    const float* fc_w  = (const float*)d_in[13];
    const float* fc_b  = (const float*)d_in[14];
    float* out = (float*)d_out;

    static bool attr_set = false;
    if (!attr_set) {
        cudaFuncSetAttribute(xproj_gemm, cudaFuncAttributeMaxDynamicSharedMemorySize, GEMM_SMEM);
        attr_set = true;
    }
    xproj_gemm<<<(B_DIM * T_DIM) / 256, 256, GEMM_SMEM>>>(x, w_ih0, b_ih0);
    rnn_scan<<<B_DIM, 960>>>(w_hh0, b_hh0,
                             w_ih1, w_hh1, b_ih1, b_hh1,
                             w_ih2, w_hh2, b_ih2, b_hh2,
                             fc_w, fc_b, out);
}

// round 5
// speedup vs baseline: 1.0702x; 1.0702x over previous
#include <cuda_runtime.h>
#include <cuda_bf16.h>
#include <cstdint>

#define I_DIM 2048
#define H_DIM 96
#define B_DIM 64
#define T_DIM 512

typedef unsigned long long ull;

// ============================ generic helpers ==============================

__device__ __forceinline__ void fma2(ull &d, ull a, ull b) {
    asm("fma.rn.f32x2 %0, %1, %2, %0;" : "+l"(d) : "l"(a), "l"(b));
}
__device__ __forceinline__ ull pack2(float lo, float hi) {
    ull v; asm("mov.b64 %0, {%1, %2};" : "=l"(v) : "f"(lo), "f"(hi)); return v;
}
__device__ __forceinline__ float fast_tanh(float x) {
    float e = __expf(2.0f * x);
    return 1.0f - __fdividef(2.0f, e + 1.0f);
}
__device__ __forceinline__ uint32_t smem_u32(const void* p) {
    uint32_t a;
    asm("{ .reg .u64 t; cvta.to.shared.u64 t, %1; cvt.u32.u64 %0, t; }" : "=r"(a) : "l"(p));
    return a;
}
__device__ __forceinline__ void lds_v2u64(ull &x, ull &y, uint32_t a) {
    asm volatile("ld.shared.v2.b64 {%0,%1}, [%2];" : "=l"(x), "=l"(y) : "r"(a));
}
__device__ __forceinline__ void sts_f32(uint32_t a, float v) {
    asm volatile("st.shared.f32 [%0], %1;" :: "r"(a), "f"(v) : "memory");
}
__device__ __forceinline__ float lds_f32(uint32_t a) {
    float v; asm volatile("ld.shared.f32 %0, [%1];" : "=f"(v) : "r"(a)); return v;
}
__device__ __forceinline__ float hsum4(ull a0, ull a1) {
    ull t; asm("add.rn.f32x2 %0, %1, %2;" : "=l"(t) : "l"(a0), "l"(a1));
    float lo, hi; asm("mov.b64 {%0,%1}, %2;" : "=f"(lo), "=f"(hi) : "l"(t));
    return lo + hi;
}
__device__ __forceinline__ int lds_acq(uint32_t a) {
    int v; asm volatile("ld.acquire.cta.shared.u32 %0, [%1];" : "=r"(v) : "r"(a) : "memory");
    return v;
}
__device__ __forceinline__ void sts_rel(uint32_t a, int v) {
    asm volatile("st.release.cta.shared.u32 [%0], %1;" :: "r"(a), "r"(v) : "memory");
}
#define SPIN_GE(addr, val) do { \
    if (lds_acq(addr) < (val)) { while (lds_acq(addr) < (val)) __nanosleep(32); } \
} while (0)

// ======================= mma.sync / ldmatrix helpers =======================

__device__ __forceinline__ void ldsm_x4(uint32_t &r0, uint32_t &r1, uint32_t &r2,
                                        uint32_t &r3, uint32_t addr) {
    asm volatile("ldmatrix.sync.aligned.m8n8.x4.shared.b16 {%0,%1,%2,%3}, [%4];"
                 : "=r"(r0), "=r"(r1), "=r"(r2), "=r"(r3) : "r"(addr));
}
__device__ __forceinline__ void mma16816(float* c, const uint32_t* a, const uint32_t* b) {
    asm volatile("mma.sync.aligned.m16n8k16.row.col.f32.bf16.bf16.f32 "
                 "{%0,%1,%2,%3}, {%4,%5,%6,%7}, {%8,%9}, {%0,%1,%2,%3};"
                 : "+f"(c[0]), "+f"(c[1]), "+f"(c[2]), "+f"(c[3])
                 : "r"(a[0]), "r"(a[1]), "r"(a[2]), "r"(a[3]), "r"(b[0]), "r"(b[1]));
}
__device__ __forceinline__ void cvt_hilo(float4 v, uint2 &hp, uint2 &lp) {
    __nv_bfloat162 h0 = __float22bfloat162_rn(make_float2(v.x, v.y));
    __nv_bfloat162 h1 = __float22bfloat162_rn(make_float2(v.z, v.w));
    float2 f0 = __bfloat1622float2(h0), f1 = __bfloat1622float2(h1);
    __nv_bfloat162 l0 = __float22bfloat162_rn(make_float2(v.x - f0.x, v.y - f0.y));
    __nv_bfloat162 l1 = __float22bfloat162_rn(make_float2(v.z - f1.x, v.w - f1.y));
    hp = make_uint2(*(uint32_t*)&h0, *(uint32_t*)&h1);
    lp = make_uint2(*(uint32_t*)&l0, *(uint32_t*)&l1);
}

// Scratch: layer-0 input projection, [B*T, 96]
__device__ float g_xproj[(size_t)B_DIM * T_DIM * H_DIM];

// ===========================================================================
// Kernel 1: xproj = x @ w_ih0^T + b_ih0, HMMA bf16 3-split. (proven, ~65us)
// ===========================================================================
#define ROWB 80
#define SM_BIAS 0
#define SM_AHI  512
#define SM_ALO  (512 + 20480)
#define SM_BHI  (512 + 40960)
#define SM_BLO  (512 + 40960 + 7680)
#define GEMM_SMEM (512 + 40960 + 15360)   // 56832 bytes

__global__ __launch_bounds__(256, 1) void xproj_gemm(const float* __restrict__ X,
                                                     const float* __restrict__ W,
                                                     const float* __restrict__ bias)
{
    extern __shared__ char smem[];
    float* sbias = (float*)(smem + SM_BIAS);
    const int tid = threadIdx.x, lane = tid & 31, warp = tid >> 5;
    const int rowbase = blockIdx.x * 256;
    const int m_warp = (warp & 3) * 64;
    const int n_warp = (warp >> 2) * 48;

    if (tid < H_DIM) sbias[tid] = __ldg(bias + tid);

    const int g = lane >> 3, r = lane & 7;
    const uint32_t lane_off = (uint32_t)((((g & 1) << 3) + r) * ROWB + ((g >> 1) << 4));
    const uint32_t sb = smem_u32(smem);
    const uint32_t aHiB = sb + SM_AHI + (uint32_t)m_warp * ROWB + lane_off;
    const uint32_t aLoB = sb + SM_ALO + (uint32_t)m_warp * ROWB + lane_off;
    const uint32_t bHiB = sb + SM_BHI + (uint32_t)n_warp * ROWB + lane_off;
    const uint32_t bLoB = sb + SM_BLO + (uint32_t)n_warp * ROWB + lane_off;

    float acc[4][6][4];
    #pragma unroll
    for (int mt = 0; mt < 4; mt++)
        #pragma unroll
        for (int nt = 0; nt < 6; nt++)
            #pragma unroll
            for (int i = 0; i < 4; i++) acc[mt][nt][i] = 0.f;

    float4 sa[8], sw[3];

    auto load_stage = [&](int k0) {
        #pragma unroll
        for (int it = 0; it < 8; ++it) {
            int f = tid + it * 256;
            sa[it] = *(const float4*)(X + (size_t)(rowbase + (f >> 3)) * I_DIM + k0 + ((f & 7) << 2));
        }
        #pragma unroll
        for (int it = 0; it < 3; ++it) {
            int f = tid + it * 256;
            sw[it] = *(const float4*)(W + (size_t)(f >> 3) * I_DIM + k0 + ((f & 7) << 2));
        }
    };
    auto store_stage = [&]() {
        #pragma unroll
        for (int it = 0; it < 8; ++it) {
            int f = tid + it * 256;
            int off = (f >> 3) * ROWB + ((f & 7) << 3);
            uint2 hp, lp; cvt_hilo(sa[it], hp, lp);
            *(uint2*)(smem + SM_AHI + off) = hp;
            *(uint2*)(smem + SM_ALO + off) = lp;
        }
        #pragma unroll
        for (int it = 0; it < 3; ++it) {
            int f = tid + it * 256;
            int off = (f >> 3) * ROWB + ((f & 7) << 3);
            uint2 hp, lp; cvt_hilo(sw[it], hp, lp);
            *(uint2*)(smem + SM_BHI + off) = hp;
            *(uint2*)(smem + SM_BLO + off) = lp;
        }
    };

    load_stage(0);
    store_stage();
    __syncthreads();

    const int NC = I_DIM / 32;   // 64
    for (int c = 0; c < NC; ++c) {
        if (c + 1 < NC) load_stage((c + 1) * 32);

        #pragma unroll
        for (int s = 0; s < 2; ++s) {
            uint32_t ah[4][4], al[4][4], bh[6][2], bl[6][2];
            #pragma unroll
            for (int mt = 0; mt < 4; ++mt) {
                ldsm_x4(ah[mt][0], ah[mt][1], ah[mt][2], ah[mt][3], aHiB + mt * (16 * ROWB) + s * 32);
                ldsm_x4(al[mt][0], al[mt][1], al[mt][2], al[mt][3], aLoB + mt * (16 * ROWB) + s * 32);
            }
            #pragma unroll
            for (int np = 0; np < 3; ++np) {
                uint32_t r0, r1, r2, r3;
                ldsm_x4(r0, r1, r2, r3, bHiB + np * (16 * ROWB) + s * 32);
                bh[2 * np][0] = r0; bh[2 * np + 1][0] = r1;
                bh[2 * np][1] = r2; bh[2 * np + 1][1] = r3;
                ldsm_x4(r0, r1, r2, r3, bLoB + np * (16 * ROWB) + s * 32);
                bl[2 * np][0] = r0; bl[2 * np + 1][0] = r1;
                bl[2 * np][1] = r2; bl[2 * np + 1][1] = r3;
            }
            #pragma unroll
            for (int mt = 0; mt < 4; ++mt)
                #pragma unroll
                for (int nt = 0; nt < 6; ++nt) {
                    mma16816(acc[mt][nt], ah[mt], bh[nt]);
                    mma16816(acc[mt][nt], ah[mt], bl[nt]);
                    mma16816(acc[mt][nt], al[mt], bh[nt]);
                }
        }
        __syncthreads();
        if (c + 1 < NC) { store_stage(); }
        __syncthreads();
    }

    #pragma unroll
    for (int nt = 0; nt < 6; ++nt) {
        int col = n_warp + nt * 8 + (lane & 3) * 2;
        float b0 = sbias[col], b1 = sbias[col + 1];
        #pragma unroll
        for (int mt = 0; mt < 4; ++mt) {
            int row0 = rowbase + m_warp + mt * 16 + (lane >> 2);
            float2 v0 = make_float2(acc[mt][nt][0] + b0, acc[mt][nt][1] + b1);
            float2 v1 = make_float2(acc[mt][nt][2] + b0, acc[mt][nt][3] + b1);
            *(float2*)(g_xproj + (size_t)row0 * H_DIM + col) = v0;
            *(float2*)(g_xproj + (size_t)(row0 + 8) * H_DIM + col) = v1;
        }
    }
}

// ===========================================================================
// Kernel 2: recurrent scan — decoupled layer groups, NO global barrier.
// 960 thr = 30 warps:
//   warps  0-5  (tid   0-191): layer0. j=warp*16+(lane&15), seg=lane>>4.
//                               bar.sync 1,192. publishes p0.
//   warps  6-17 (tid 192-575): layer1. j=wl*8+(lane&7), c=lane>>3, seg=c&1.
//                               bar.sync 2,384. waits p0,c2; publishes p1,c1.
//   warps 18-29 (tid 576-959): layer2. same shape. bar.sync 3,384.
//                               waits p1; publishes c2.
// h state: 24 chunks (arr0..2 x slot0..3 x seg0..1) of 48 floats at 52-float
// stride -> bank group (2*slot+5*seg)%8, distinct for every co-accessed set
// => every LDS is a single conflict-free wavefront.
// Ring depth 4 per array; producer/consumer flow via release/acquire flags.
// ===========================================================================
#define CH_STRIDE 208            // 52 floats * 4B
#define SLOT_STRIDE 416          // 2 chunks per slot

__global__ __launch_bounds__(960, 1) void rnn_scan(
    const float* __restrict__ whh0, const float* __restrict__ bhh0,
    const float* __restrict__ wih1, const float* __restrict__ whh1,
    const float* __restrict__ bih1, const float* __restrict__ bhh1,
    const float* __restrict__ wih2, const float* __restrict__ whh2,
    const float* __restrict__ bih2, const float* __restrict__ bhh2,
    const float* __restrict__ fcw,  const float* __restrict__ fcb,
    float* __restrict__ out)
{
    __shared__ __align__(16) float hs[24 * 52];   // 24 chunks x 52 floats
    __shared__ int fl[4];                          // p0, p1, c1, c2
    __shared__ float sred[96];

    const int tid = threadIdx.x, lane = tid & 31, warp = tid >> 5;
    const int b = blockIdx.x;

    for (int i = tid; i < 24 * 52; i += 960) hs[i] = 0.f;
    if (tid < 4) fl[tid] = -1;

    const uint32_t sbase = smem_u32(hs);
    const uint32_t f_p0 = smem_u32(&fl[0]);
    const uint32_t f_p1 = smem_u32(&fl[1]);
    const uint32_t f_c1 = smem_u32(&fl[2]);
    const uint32_t f_c2 = smem_u32(&fl[3]);

    __syncthreads();

    if (warp < 6) {
        // ----------------- layer 0 -----------------
        const int j = warp * 16 + (lane & 15);
        const int seg = lane >> 4;
        const float* wr = whh0 + j * 96 + seg * 48;
        ull w[24];
        #pragma unroll
        for (int q = 0; q < 24; q++) w[q] = pack2(__ldg(wr + 2 * q), __ldg(wr + 2 * q + 1));
        const float bias = __ldg(bhh0 + j);
        const uint32_t src_base = sbase + (uint32_t)seg * CH_STRIDE;          // arr0
        const int jm = (j >= 48) ? j - 48 : j;
        const uint32_t wbase = sbase + (uint32_t)((j >= 48) ? CH_STRIDE : 0) + (uint32_t)jm * 4;
        const float* xpp = g_xproj + ((size_t)b * T_DIM) * H_DIM + j;
        float xp = __ldg(xpp);

        for (int t = 0; t < T_DIM; ++t) {
            const uint32_t src = src_base + (uint32_t)(((t + 3) & 3) * SLOT_STRIDE);
            ull a0 = 0, a1 = 0;
            #pragma unroll
            for (int m = 0; m < 12; m++) {
                ull vx, vy; lds_v2u64(vx, vy, src + 16 * m);
                fma2(a0, w[2 * m], vx);
                fma2(a1, w[2 * m + 1], vy);
            }
            float s = hsum4(a0, a1);
            s += __shfl_xor_sync(0xffffffffu, s, 16);
            float hv = fast_tanh(s + xp + bias);
            int nt = (t + 1 < T_DIM) ? t + 1 : T_DIM - 1;
            xp = __ldg(xpp + nt * H_DIM);
            SPIN_GE(f_c1, t - 4);                       // ring-overwrite guard
            if (lane < 16) sts_f32(wbase + (uint32_t)((t & 3) * SLOT_STRIDE), hv);
            asm volatile("bar.sync 1, 192;" ::: "memory");
            if (tid == 0) sts_rel(f_p0, t);
        }
    } else if (warp < 18) {
        // ----------------- layer 1 -----------------
        const int wl = warp - 6;
        const int j = wl * 8 + (lane & 7);
        const int c = lane >> 3, seg = c & 1;
        const float* wr = ((c < 2) ? wih1 : whh1) + j * 96 + seg * 48;
        ull w[24];
        #pragma unroll
        for (int q = 0; q < 24; q++) w[q] = pack2(__ldg(wr + 2 * q), __ldg(wr + 2 * q + 1));
        const float bias = __ldg(bih1 + j) + __ldg(bhh1 + j);
        const uint32_t src_base = sbase + (uint32_t)(((c < 2) ? 0 : 8) + seg) * CH_STRIDE;
        const int jm = (j >= 48) ? j - 48 : j;
        const uint32_t wbase = sbase + 8u * CH_STRIDE
                             + (uint32_t)((j >= 48) ? CH_STRIDE : 0) + (uint32_t)jm * 4;
        const bool rdA = (c < 2);

        for (int v = 0; v < T_DIM; ++v) {
            SPIN_GE(f_p0, v);                           // h0[v] ready
            const int slA = rdA ? (v & 3) : ((v + 3) & 3);
            const uint32_t src = src_base + (uint32_t)(slA * SLOT_STRIDE);
            ull a0 = 0, a1 = 0;
            #pragma unroll
            for (int m = 0; m < 12; m++) {
                ull vx, vy; lds_v2u64(vx, vy, src + 16 * m);
                fma2(a0, w[2 * m], vx);
                fma2(a1, w[2 * m + 1], vy);
            }
            float s = hsum4(a0, a1);
            s += __shfl_xor_sync(0xffffffffu, s, 8);
            s += __shfl_xor_sync(0xffffffffu, s, 16);
            float hv = fast_tanh(s + bias);
            SPIN_GE(f_c2, v - 4);                       // ring-overwrite guard
            if (lane < 8) sts_f32(wbase + (uint32_t)((v & 3) * SLOT_STRIDE), hv);
            asm volatile("bar.sync 2, 384;" ::: "memory");
            if (tid == 192) { sts_rel(f_c1, v); sts_rel(f_p1, v); }
        }
    } else {
        // ----------------- layer 2 -----------------
        const int wl = warp - 18;
        const int j = wl * 8 + (lane & 7);
        const int c = lane >> 3, seg = c & 1;
        const float* wr = ((c < 2) ? wih2 : whh2) + j * 96 + seg * 48;
        ull w[24];
        #pragma unroll
        for (int q = 0; q < 24; q++) w[q] = pack2(__ldg(wr + 2 * q), __ldg(wr + 2 * q + 1));
        const float bias = __ldg(bih2 + j) + __ldg(bhh2 + j);
        const uint32_t src_base = sbase + (uint32_t)(((c < 2) ? 8 : 16) + seg) * CH_STRIDE;
        const int jm = (j >= 48) ? j - 48 : j;
        const uint32_t wbase = sbase + 16u * CH_STRIDE
                             + (uint32_t)((j >= 48) ? CH_STRIDE : 0) + (uint32_t)jm * 4;
        const bool rdA = (c < 2);

        for (int v = 0; v < T_DIM; ++v) {
            SPIN_GE(f_p1, v);                           // h1[v] ready
            const int slA = rdA ? (v & 3) : ((v + 3) & 3);
            const uint32_t src = src_base + (uint32_t)(slA * SLOT_STRIDE);
            ull a0 = 0, a1 = 0;
            #pragma unroll
            for (int m = 0; m < 12; m++) {
                ull vx, vy; lds_v2u64(vx, vy, src + 16 * m);
                fma2(a0, w[2 * m], vx);
                fma2(a1, w[2 * m + 1], vy);
            }
            float s = hsum4(a0, a1);
            s += __shfl_xor_sync(0xffffffffu, s, 8);
            s += __shfl_xor_sync(0xffffffffu, s, 16);
            float hv = fast_tanh(s + bias);
            if (lane < 8) sts_f32(wbase + (uint32_t)((v & 3) * SLOT_STRIDE), hv);
            asm volatile("bar.sync 3, 384;" ::: "memory");
            if (tid == 576) sts_rel(f_c2, v);
        }
    }

    __syncthreads();

    // FC head: out[b] = h2[511] . fc_w + fc_b ; slot 511&3 = 3 -> chunks 22/23
    if (tid < 96) {
        int seg = (tid >= 48) ? 1 : 0;
        int jm = tid - 48 * seg;
        float hval = lds_f32(sbase + (uint32_t)(22 + seg) * CH_STRIDE + (uint32_t)jm * 4);
        sred[tid] = hval * __ldg(fcw + tid);
    }
    __syncthreads();
    if (tid == 0) {
        float s = __ldg(fcb);
        #pragma unroll
        for (int k = 0; k < 96; k++) s += sred[k];
        out[b] = s;
    }
}

extern "C" void kernel_launch(void* const* d_in, const int* in_sizes, int n_in,
                              void* d_out, int out_size) {
    const float* x     = (const float*)d_in[0];
    const float* w_ih0 = (const float*)d_in[1];
    const float* w_hh0 = (const float*)d_in[2];
    const float* b_ih0 = (const float*)d_in[3];
    const float* b_hh0 = (const float*)d_in[4];
    const float* w_ih1 = (const float*)d_in[5];
    const float* w_hh1 = (const float*)d_in[6];
    const float* b_ih1 = (const float*)d_in[7];
    const float* b_hh1 = (const float*)d_in[8];
    const float* w_ih2 = (const float*)d_in[9];
    const float* w_hh2 = (const float*)d_in[10];
    const float* b_ih2 = (const float*)d_in[11];
    const float* b_hh2 = (const float*)d_in[12];
    const float* fc_w  = (const float*)d_in[13];
    const float* fc_b  = (const float*)d_in[14];
    float* out = (float*)d_out;

    cudaFuncSetAttribute(xproj_gemm, cudaFuncAttributeMaxDynamicSharedMemorySize, GEMM_SMEM);
    xproj_gemm<<<(B_DIM * T_DIM) / 256, 256, GEMM_SMEM>>>(x, w_ih0, b_ih0);
    rnn_scan<<<B_DIM, 960>>>(w_hh0, b_hh0,
                             w_ih1, w_hh1, b_ih1, b_hh1,
                             w_ih2, w_hh2, b_ih2, b_hh2,
                             fc_w, fc_b, out);
}

// round 7
// speedup vs baseline: 1.2102x; 1.1309x over previous
#include <cuda_runtime.h>
#include <cuda_bf16.h>
#include <cstdint>

#define I_DIM 2048
#define H_DIM 96
#define B_DIM 64
#define T_DIM 512

typedef unsigned long long ull;

// ============================ generic helpers ==============================

__device__ __forceinline__ void fma2(ull &d, ull a, ull b) {
    asm("fma.rn.f32x2 %0, %1, %2, %0;" : "+l"(d) : "l"(a), "l"(b));
}
__device__ __forceinline__ ull pack2(float lo, float hi) {
    ull v; asm("mov.b64 %0, {%1, %2};" : "=l"(v) : "f"(lo), "f"(hi)); return v;
}
__device__ __forceinline__ float fast_tanh(float x) {
    float e = __expf(2.0f * x);
    return 1.0f - __fdividef(2.0f, e + 1.0f);
}
__device__ __forceinline__ uint32_t smem_u32(const void* p) {
    uint32_t a;
    asm("{ .reg .u64 t; cvta.to.shared.u64 t, %1; cvt.u32.u64 %0, t; }" : "=r"(a) : "l"(p));
    return a;
}
__device__ __forceinline__ void lds_v2u64(ull &x, ull &y, uint32_t a) {
    asm volatile("ld.shared.v2.b64 {%0,%1}, [%2];" : "=l"(x), "=l"(y) : "r"(a));
}
__device__ __forceinline__ void sts_f32(uint32_t a, float v) {
    asm volatile("st.shared.f32 [%0], %1;" :: "r"(a), "f"(v) : "memory");
}
__device__ __forceinline__ float lds_f32(uint32_t a) {
    float v; asm volatile("ld.shared.f32 %0, [%1];" : "=f"(v) : "r"(a)); return v;
}
__device__ __forceinline__ float hsum4(ull a0, ull a1) {
    ull t; asm("add.rn.f32x2 %0, %1, %2;" : "=l"(t) : "l"(a0), "l"(a1));
    float lo, hi; asm("mov.b64 {%0,%1}, %2;" : "=f"(lo), "=f"(hi) : "l"(t));
    return lo + hi;
}
// cross-CTA progress flags (gpu scope)
__device__ __forceinline__ int ldg_acq(const int* p) {
    int v; asm volatile("ld.global.acquire.gpu.u32 %0, [%1];" : "=r"(v) : "l"(p) : "memory");
    return v;
}
__device__ __forceinline__ void stg_rel(int* p, int v) {
    asm volatile("st.global.release.gpu.u32 [%0], %1;" :: "l"(p), "r"(v) : "memory");
}
#define GPOLL(p, val) do { \
    if (ldg_acq(p) < (val)) { while (ldg_acq(p) < (val)) __nanosleep(64); } \
} while (0)

// ======================= mma.sync / ldmatrix helpers =======================

__device__ __forceinline__ void ldsm_x4(uint32_t &r0, uint32_t &r1, uint32_t &r2,
                                        uint32_t &r3, uint32_t addr) {
    asm volatile("ldmatrix.sync.aligned.m8n8.x4.shared.b16 {%0,%1,%2,%3}, [%4];"
                 : "=r"(r0), "=r"(r1), "=r"(r2), "=r"(r3) : "r"(addr));
}
__device__ __forceinline__ void mma16816(float* c, const uint32_t* a, const uint32_t* b) {
    asm volatile("mma.sync.aligned.m16n8k16.row.col.f32.bf16.bf16.f32 "
                 "{%0,%1,%2,%3}, {%4,%5,%6,%7}, {%8,%9}, {%0,%1,%2,%3};"
                 : "+f"(c[0]), "+f"(c[1]), "+f"(c[2]), "+f"(c[3])
                 : "r"(a[0]), "r"(a[1]), "r"(a[2]), "r"(a[3]), "r"(b[0]), "r"(b[1]));
}
__device__ __forceinline__ void cvt_hilo(float4 v, uint2 &hp, uint2 &lp) {
    __nv_bfloat162 h0 = __float22bfloat162_rn(make_float2(v.x, v.y));
    __nv_bfloat162 h1 = __float22bfloat162_rn(make_float2(v.z, v.w));
    float2 f0 = __bfloat1622float2(h0), f1 = __bfloat1622float2(h1);
    __nv_bfloat162 l0 = __float22bfloat162_rn(make_float2(v.x - f0.x, v.y - f0.y));
    __nv_bfloat162 l1 = __float22bfloat162_rn(make_float2(v.z - f1.x, v.w - f1.y));
    hp = make_uint2(*(uint32_t*)&h0, *(uint32_t*)&h1);
    lp = make_uint2(*(uint32_t*)&l0, *(uint32_t*)&l1);
}

// ===================== global scratch (no allocations) =====================
__device__ float g_xproj[(size_t)B_DIM * T_DIM * H_DIM];
__device__ float g_h0[(size_t)B_DIM * T_DIM * H_DIM];
__device__ float g_h1[(size_t)B_DIM * T_DIM * H_DIM];
__device__ int   g_prog[2 * B_DIM];   // [0..63]: l0 progress, [64..127]: l1

// ===========================================================================
// Kernel 1: xproj = x @ w_ih0^T + b_ih0, HMMA bf16 3-split. (proven, ~65us)
// Also zeroes the cross-CTA progress flags for the scan (block 0).
// ===========================================================================
#define ROWB 80
#define SM_BIAS 0
#define SM_AHI  512
#define SM_ALO  (512 + 20480)
#define SM_BHI  (512 + 40960)
#define SM_BLO  (512 + 40960 + 7680)
#define GEMM_SMEM (512 + 40960 + 15360)   // 56832 bytes

__global__ __launch_bounds__(256, 1) void xproj_gemm(const float* __restrict__ X,
                                                     const float* __restrict__ W,
                                                     const float* __restrict__ bias)
{
    extern __shared__ char smem[];
    float* sbias = (float*)(smem + SM_BIAS);
    const int tid = threadIdx.x, lane = tid & 31, warp = tid >> 5;
    const int rowbase = blockIdx.x * 256;
    const int m_warp = (warp & 3) * 64;
    const int n_warp = (warp >> 2) * 48;

    if (blockIdx.x == 0 && tid < 2 * B_DIM) g_prog[tid] = 0;   // reset scan flags
    if (tid < H_DIM) sbias[tid] = __ldg(bias + tid);

    const int g = lane >> 3, r = lane & 7;
    const uint32_t lane_off = (uint32_t)((((g & 1) << 3) + r) * ROWB + ((g >> 1) << 4));
    const uint32_t sb = smem_u32(smem);
    const uint32_t aHiB = sb + SM_AHI + (uint32_t)m_warp * ROWB + lane_off;
    const uint32_t aLoB = sb + SM_ALO + (uint32_t)m_warp * ROWB + lane_off;
    const uint32_t bHiB = sb + SM_BHI + (uint32_t)n_warp * ROWB + lane_off;
    const uint32_t bLoB = sb + SM_BLO + (uint32_t)n_warp * ROWB + lane_off;

    float acc[4][6][4];
    #pragma unroll
    for (int mt = 0; mt < 4; mt++)
        #pragma unroll
        for (int nt = 0; nt < 6; nt++)
            #pragma unroll
            for (int i = 0; i < 4; i++) acc[mt][nt][i] = 0.f;

    float4 sa[8], sw[3];

    auto load_stage = [&](int k0) {
        #pragma unroll
        for (int it = 0; it < 8; ++it) {
            int f = tid + it * 256;
            sa[it] = *(const float4*)(X + (size_t)(rowbase + (f >> 3)) * I_DIM + k0 + ((f & 7) << 2));
        }
        #pragma unroll
        for (int it = 0; it < 3; ++it) {
            int f = tid + it * 256;
            sw[it] = *(const float4*)(W + (size_t)(f >> 3) * I_DIM + k0 + ((f & 7) << 2));
        }
    };
    auto store_stage = [&]() {
        #pragma unroll
        for (int it = 0; it < 8; ++it) {
            int f = tid + it * 256;
            int off = (f >> 3) * ROWB + ((f & 7) << 3);
            uint2 hp, lp; cvt_hilo(sa[it], hp, lp);
            *(uint2*)(smem + SM_AHI + off) = hp;
            *(uint2*)(smem + SM_ALO + off) = lp;
        }
        #pragma unroll
        for (int it = 0; it < 3; ++it) {
            int f = tid + it * 256;
            int off = (f >> 3) * ROWB + ((f & 7) << 3);
            uint2 hp, lp; cvt_hilo(sw[it], hp, lp);
            *(uint2*)(smem + SM_BHI + off) = hp;
            *(uint2*)(smem + SM_BLO + off) = lp;
        }
    };

    load_stage(0);
    store_stage();
    __syncthreads();

    const int NC = I_DIM / 32;   // 64
    for (int c = 0; c < NC; ++c) {
        if (c + 1 < NC) load_stage((c + 1) * 32);

        #pragma unroll
        for (int s = 0; s < 2; ++s) {
            uint32_t ah[4][4], al[4][4], bh[6][2], bl[6][2];
            #pragma unroll
            for (int mt = 0; mt < 4; ++mt) {
                ldsm_x4(ah[mt][0], ah[mt][1], ah[mt][2], ah[mt][3], aHiB + mt * (16 * ROWB) + s * 32);
                ldsm_x4(al[mt][0], al[mt][1], al[mt][2], al[mt][3], aLoB + mt * (16 * ROWB) + s * 32);
            }
            #pragma unroll
            for (int np = 0; np < 3; ++np) {
                uint32_t r0, r1, r2, r3;
                ldsm_x4(r0, r1, r2, r3, bHiB + np * (16 * ROWB) + s * 32);
                bh[2 * np][0] = r0; bh[2 * np + 1][0] = r1;
                bh[2 * np][1] = r2; bh[2 * np + 1][1] = r3;
                ldsm_x4(r0, r1, r2, r3, bLoB + np * (16 * ROWB) + s * 32);
                bl[2 * np][0] = r0; bl[2 * np + 1][0] = r1;
                bl[2 * np][1] = r2; bl[2 * np + 1][1] = r3;
            }
            #pragma unroll
            for (int mt = 0; mt < 4; ++mt)
                #pragma unroll
                for (int nt = 0; nt < 6; ++nt) {
                    mma16816(acc[mt][nt], ah[mt], bh[nt]);
                    mma16816(acc[mt][nt], ah[mt], bl[nt]);
                    mma16816(acc[mt][nt], al[mt], bh[nt]);
                }
        }
        __syncthreads();
        if (c + 1 < NC) { store_stage(); }
        __syncthreads();
    }

    #pragma unroll
    for (int nt = 0; nt < 6; ++nt) {
        int col = n_warp + nt * 8 + (lane & 3) * 2;
        float b0 = sbias[col], b1 = sbias[col + 1];
        #pragma unroll
        for (int mt = 0; mt < 4; ++mt) {
            int row0 = rowbase + m_warp + mt * 16 + (lane >> 2);
            float2 v0 = make_float2(acc[mt][nt][0] + b0, acc[mt][nt][1] + b1);
            float2 v1 = make_float2(acc[mt][nt][2] + b0, acc[mt][nt][3] + b1);
            *(float2*)(g_xproj + (size_t)row0 * H_DIM + col) = v0;
            *(float2*)(g_xproj + (size_t)(row0 + 8) * H_DIM + col) = v1;
        }
    }
}

// ===========================================================================
// Kernel 2: recurrent scan — one CTA per (batch, layer). Grid 192, 192 thr.
// Pair mapping: j = tid>>1 (output), c = tid&1:
//   layer0:    c = K-half of whh0 row j (24 ull weights).
//   layer1/2:  c=0 -> full wih row j, reads stage ring (x input stream)
//              c=1 -> full whh row j, reads hown          (48 ull weights)
// Pair combine via shfl_xor(1); even lane finalizes (tanh, writes).
// Within CTA: ONE __syncthreads per step. Across layers: global streams +
// progress flags (release/acquire gpu), published every 8 steps; consumer
// prefetches 12+ steps ahead via LDG->reg->smem ring (16 slots).
// Producers never wait on consumers => deadlock-free at any residency.
// Smem: stage @0 (16*384B), hown @6176 (2*384B; +32 mod 128 vs stage so the
// two 16B address groups per warp-LDS hit disjoint banks), sred @6944.
// ===========================================================================
#define SCAN_SMEM_BYTES 7328
#define ST_OFF 0
#define HN_OFF 6176
#define SR_OFF 6944

__global__ __launch_bounds__(192, 2) void rnn_layer(
    const float* __restrict__ whh0, const float* __restrict__ bhh0,
    const float* __restrict__ wih1, const float* __restrict__ whh1,
    const float* __restrict__ bih1, const float* __restrict__ bhh1,
    const float* __restrict__ wih2, const float* __restrict__ whh2,
    const float* __restrict__ bih2, const float* __restrict__ bhh2,
    const float* __restrict__ fcw,  const float* __restrict__ fcb,
    float* __restrict__ out)
{
    __shared__ __align__(128) char smbuf[SCAN_SMEM_BYTES];

    const int layer = blockIdx.x >> 6;      // 0,1,2
    const int b     = blockIdx.x & 63;
    const int tid   = threadIdx.x;
    const int j     = tid >> 1;             // 0..95
    const int c     = tid & 1;

    const uint32_t stb = smem_u32(smbuf) + ST_OFF;
    const uint32_t hb  = smem_u32(smbuf) + HN_OFF;

    // zero hown (2 x 96 floats)
    if (tid < 192) sts_f32(hb + tid * 4, 0.f);

    const size_t soff = (size_t)b * T_DIM * H_DIM;
    const float* instream;
    float*       outstream = nullptr;
    const int*   inflag    = nullptr;
    int*         outflag   = nullptr;
    float bias = 0.f;

    if (layer == 0) {
        instream  = g_xproj + soff;
        outstream = g_h0 + soff;
        outflag   = &g_prog[b];
        if (c == 0) bias = __ldg(bhh0 + j);
    } else if (layer == 1) {
        instream  = g_h0 + soff;
        outstream = g_h1 + soff;
        inflag    = &g_prog[b];
        outflag   = &g_prog[64 + b];
        if (c == 0) bias = __ldg(bih1 + j) + __ldg(bhh1 + j);
    } else {
        instream  = g_h1 + soff;
        inflag    = &g_prog[64 + b];
        if (c == 0) bias = __ldg(bih2 + j) + __ldg(bhh2 + j);
    }

    if (layer == 0) {
        // ---------------- layer 0: h = tanh(xproj + whh0 h + bhh0) ----------
        // thread (j,c): K-half c of whh0 row j (48 floats = 24 ull)
        ull w[24];
        {
            const float* wr = whh0 + j * H_DIM + c * 48;
            #pragma unroll
            for (int q = 0; q < 24; q++) w[q] = pack2(__ldg(wr + 2 * q), __ldg(wr + 2 * q + 1));
        }
        const float* xpp = instream + j;
        float xc[4], xn[4];
        if (c == 0) {
            #pragma unroll
            for (int s = 0; s < 4; s++) xc[s] = __ldg(xpp + s * H_DIM);
            #pragma unroll
            for (int s = 0; s < 4; s++) xn[s] = __ldg(xpp + (4 + s) * H_DIM);
        }
        __syncthreads();

        const uint32_t src_half = hb + (uint32_t)(c * 192);
        const uint32_t dst_j    = hb + (uint32_t)(j * 4);

        for (int it = 0; it < T_DIM / 4; ++it) {
            #pragma unroll
            for (int s = 0; s < 4; s++) {
                const int v = 4 * it + s;
                const uint32_t src = src_half + (uint32_t)((((v & 1) ^ 1)) * 384);
                ull a0 = 0, a1 = 0;
                #pragma unroll
                for (int m = 0; m < 12; m++) {
                    ull vx, vy; lds_v2u64(vx, vy, src + 16 * m);
                    fma2(a0, w[2 * m], vx);
                    fma2(a1, w[2 * m + 1], vy);
                }
                float sdot = hsum4(a0, a1);
                sdot += __shfl_xor_sync(0xffffffffu, sdot, 1);
                if (c == 0) {
                    float hv = fast_tanh(sdot + xc[s] + bias);
                    sts_f32(dst_j + (uint32_t)((v & 1) * 384), hv);
                    outstream[(size_t)v * H_DIM + j] = hv;
                }
                __syncthreads();
                if (((v & 7) == 7) && tid == 0) stg_rel(outflag, v + 1);
            }
            if (c == 0) {
                #pragma unroll
                for (int s = 0; s < 4; s++) xc[s] = xn[s];
                const int tb = 4 * it + 8;
                #pragma unroll
                for (int s = 0; s < 4; s++) {
                    int t = tb + s; if (t > T_DIM - 1) t = T_DIM - 1;
                    xn[s] = __ldg(xpp + (size_t)t * H_DIM);
                }
            }
        }
    } else {
        // -------- layer 1/2: h = tanh(wih x_in + whh h + bias) --------------
        // thread (j,c): c=0 full wih row (reads stage), c=1 full whh row.
        ull w[48];
        {
            const float* wr = ((layer == 1) ? (c ? whh1 : wih1)
                                            : (c ? whh2 : wih2)) + j * H_DIM;
            #pragma unroll
            for (int q = 0; q < 48; q++) w[q] = pack2(__ldg(wr + 2 * q), __ldg(wr + 2 * q + 1));
        }

        // warmup: steps 0..7 -> stage slots 0..7 ; 8..11 -> lr (c==0 threads)
        float lr[4];
        if (c == 0) {
            GPOLL(inflag, 12);
            #pragma unroll
            for (int s = 0; s < 8; s++)
                sts_f32(stb + (uint32_t)(s * 384 + j * 4), instream[s * H_DIM + j]);
            #pragma unroll
            for (int s = 0; s < 4; s++) lr[s] = instream[(8 + s) * H_DIM + j];
        }
        __syncthreads();

        const uint32_t dst_j = hb + (uint32_t)(j * 4);

        for (int it = 0; it < T_DIM / 4; ++it) {
            const int tb = 4 * it + 8;
            if (c == 0) {
                // commit steps tb..tb+3 into ring (consumed 2 iterations later)
                if (tb < T_DIM) {
                    #pragma unroll
                    for (int s = 0; s < 4; s++)
                        sts_f32(stb + (uint32_t)(((tb + s) & 15) * 384 + j * 4), lr[s]);
                }
                // fetch steps 4it+12..15 (flag-gated)
                if (4 * it + 12 < T_DIM) {
                    GPOLL(inflag, 4 * it + 16);
                    #pragma unroll
                    for (int s = 0; s < 4; s++)
                        lr[s] = instream[(size_t)(4 * it + 12 + s) * H_DIM + j];
                }
            }
            #pragma unroll
            for (int s = 0; s < 4; s++) {
                const int v = 4 * it + s;
                const uint32_t src = c ? (hb + (uint32_t)((((v & 1) ^ 1)) * 384))
                                       : (stb + (uint32_t)((v & 15) * 384));
                ull a0 = 0, a1 = 0;
                #pragma unroll
                for (int m = 0; m < 24; m++) {
                    ull vx, vy; lds_v2u64(vx, vy, src + 16 * m);
                    fma2(a0, w[2 * m], vx);
                    fma2(a1, w[2 * m + 1], vy);
                }
                float sdot = hsum4(a0, a1);
                sdot += __shfl_xor_sync(0xffffffffu, sdot, 1);
                if (c == 0) {
                    float hv = fast_tanh(sdot + bias);
                    sts_f32(dst_j + (uint32_t)((v & 1) * 384), hv);
                    if (layer == 1) outstream[(size_t)v * H_DIM + j] = hv;
                }
                __syncthreads();
                if (layer == 1 && ((v & 7) == 7) && tid == 0) stg_rel(outflag, v + 1);
            }
        }

        if (layer == 2) {
            // out[b] = h2[T-1] . fc_w + fc_b   (T-1 = 511 -> parity 1)
            const uint32_t srb = smem_u32(smbuf) + SR_OFF;
            if (tid < 96)
                sts_f32(srb + tid * 4, lds_f32(hb + 384 + tid * 4) * __ldg(fcw + tid));
            __syncthreads();
            if (tid == 0) {
                float s = __ldg(fcb);
                #pragma unroll
                for (int k = 0; k < H_DIM; k++) s += lds_f32(srb + k * 4);
                out[b] = s;
            }
        }
    }
}

extern "C" void kernel_launch(void* const* d_in, const int* in_sizes, int n_in,
                              void* d_out, int out_size) {
    const float* x     = (const float*)d_in[0];
    const float* w_ih0 = (const float*)d_in[1];
    const float* w_hh0 = (const float*)d_in[2];
    const float* b_ih0 = (const float*)d_in[3];
    const float* b_hh0 = (const float*)d_in[4];
    const float* w_ih1 = (const float*)d_in[5];
    const float* w_hh1 = (const float*)d_in[6];
    const float* b_ih1 = (const float*)d_in[7];
    const float* b_hh1 = (const float*)d_in[8];
    const float* w_ih2 = (const float*)d_in[9];
    const float* w_hh2 = (const float*)d_in[10];
    const float* b_ih2 = (const float*)d_in[11];
    const float* b_hh2 = (const float*)d_in[12];
    const float* fc_w  = (const float*)d_in[13];
    const float* fc_b  = (const float*)d_in[14];
    float* out = (float*)d_out;

    cudaFuncSetAttribute(xproj_gemm, cudaFuncAttributeMaxDynamicSharedMemorySize, GEMM_SMEM);
    xproj_gemm<<<(B_DIM * T_DIM) / 256, 256, GEMM_SMEM>>>(x, w_ih0, b_ih0);
    rnn_layer<<<3 * B_DIM, 192>>>(w_hh0, b_hh0,
                                  w_ih1, w_hh1, b_ih1, b_hh1,
                                  w_ih2, w_hh2, b_ih2, b_hh2,
                                  fc_w, fc_b, out);
}

// round 8
// speedup vs baseline: 1.4477x; 1.1962x over previous
#include <cuda_runtime.h>
#include <cuda_bf16.h>
#include <cstdint>

#define I_DIM 2048
#define H_DIM 96
#define B_DIM 64
#define T_DIM 512

typedef unsigned long long ull;

// ============================ generic helpers ==============================

__device__ __forceinline__ void fma2(ull &d, ull a, ull b) {
    asm("fma.rn.f32x2 %0, %1, %2, %0;" : "+l"(d) : "l"(a), "l"(b));
}
__device__ __forceinline__ ull pack2(float lo, float hi) {
    ull v; asm("mov.b64 %0, {%1, %2};" : "=l"(v) : "f"(lo), "f"(hi)); return v;
}
__device__ __forceinline__ float fast_tanh(float x) {
    float e = __expf(2.0f * x);
    return 1.0f - __fdividef(2.0f, e + 1.0f);
}
__device__ __forceinline__ uint32_t smem_u32(const void* p) {
    uint32_t a;
    asm("{ .reg .u64 t; cvta.to.shared.u64 t, %1; cvt.u32.u64 %0, t; }" : "=r"(a) : "l"(p));
    return a;
}
__device__ __forceinline__ void lds_v2u64(ull &x, ull &y, uint32_t a) {
    asm volatile("ld.shared.v2.b64 {%0,%1}, [%2];" : "=l"(x), "=l"(y) : "r"(a));
}
__device__ __forceinline__ void sts_f32(uint32_t a, float v) {
    asm volatile("st.shared.f32 [%0], %1;" :: "r"(a), "f"(v) : "memory");
}
__device__ __forceinline__ float lds_f32(uint32_t a) {
    float v; asm volatile("ld.shared.f32 %0, [%1];" : "=f"(v) : "r"(a)); return v;
}
// sum of 4 packed f32x2 accumulators -> scalar
__device__ __forceinline__ float hsum4x(ull a0, ull a1, ull a2, ull a3) {
    ull t, u, v;
    asm("add.rn.f32x2 %0, %1, %2;" : "=l"(t) : "l"(a0), "l"(a1));
    asm("add.rn.f32x2 %0, %1, %2;" : "=l"(u) : "l"(a2), "l"(a3));
    asm("add.rn.f32x2 %0, %1, %2;" : "=l"(v) : "l"(t), "l"(u));
    float lo, hi; asm("mov.b64 {%0,%1}, %2;" : "=f"(lo), "=f"(hi) : "l"(v));
    return lo + hi;
}
// cross-CTA progress flags (gpu scope)
__device__ __forceinline__ int ldg_acq(const int* p) {
    int v; asm volatile("ld.global.acquire.gpu.u32 %0, [%1];" : "=r"(v) : "l"(p) : "memory");
    return v;
}
__device__ __forceinline__ void stg_rel(int* p, int v) {
    asm volatile("st.global.release.gpu.u32 [%0], %1;" :: "l"(p), "r"(v) : "memory");
}
#define GPOLL(p, val) do { \
    if (ldg_acq(p) < (val)) { while (ldg_acq(p) < (val)) __nanosleep(64); } \
} while (0)

// 96-float dot: broadcast LDS from src, weights in wreg[48] (ull pairs),
// 4 accumulator chains (depth 12).
__device__ __forceinline__ float dot96(uint32_t src, const ull* wreg) {
    ull a0 = 0, a1 = 0, a2 = 0, a3 = 0;
    #pragma unroll
    for (int k = 0; k < 24; k++) {
        ull vx, vy; lds_v2u64(vx, vy, src + 16 * k);
        if (k & 1) { fma2(a2, wreg[2 * k], vx); fma2(a3, wreg[2 * k + 1], vy); }
        else       { fma2(a0, wreg[2 * k], vx); fma2(a1, wreg[2 * k + 1], vy); }
    }
    return hsum4x(a0, a1, a2, a3);
}

// ======================= mma.sync / ldmatrix helpers =======================

__device__ __forceinline__ void ldsm_x4(uint32_t &r0, uint32_t &r1, uint32_t &r2,
                                        uint32_t &r3, uint32_t addr) {
    asm volatile("ldmatrix.sync.aligned.m8n8.x4.shared.b16 {%0,%1,%2,%3}, [%4];"
                 : "=r"(r0), "=r"(r1), "=r"(r2), "=r"(r3) : "r"(addr));
}
__device__ __forceinline__ void mma16816(float* c, const uint32_t* a, const uint32_t* b) {
    asm volatile("mma.sync.aligned.m16n8k16.row.col.f32.bf16.bf16.f32 "
                 "{%0,%1,%2,%3}, {%4,%5,%6,%7}, {%8,%9}, {%0,%1,%2,%3};"
                 : "+f"(c[0]), "+f"(c[1]), "+f"(c[2]), "+f"(c[3])
                 : "r"(a[0]), "r"(a[1]), "r"(a[2]), "r"(a[3]), "r"(b[0]), "r"(b[1]));
}
__device__ __forceinline__ void cvt_hilo(float4 v, uint2 &hp, uint2 &lp) {
    __nv_bfloat162 h0 = __float22bfloat162_rn(make_float2(v.x, v.y));
    __nv_bfloat162 h1 = __float22bfloat162_rn(make_float2(v.z, v.w));
    float2 f0 = __bfloat1622float2(h0), f1 = __bfloat1622float2(h1);
    __nv_bfloat162 l0 = __float22bfloat162_rn(make_float2(v.x - f0.x, v.y - f0.y));
    __nv_bfloat162 l1 = __float22bfloat162_rn(make_float2(v.z - f1.x, v.w - f1.y));
    hp = make_uint2(*(uint32_t*)&h0, *(uint32_t*)&h1);
    lp = make_uint2(*(uint32_t*)&l0, *(uint32_t*)&l1);
}

// ===================== global scratch (no allocations) =====================
__device__ float g_xproj[(size_t)B_DIM * T_DIM * H_DIM];
__device__ float g_h0[(size_t)B_DIM * T_DIM * H_DIM];
__device__ float g_h1[(size_t)B_DIM * T_DIM * H_DIM];
__device__ int   g_prog[2 * B_DIM];   // [0..63]: l0 progress, [64..127]: l1

// ===========================================================================
// Kernel 1: xproj = x @ w_ih0^T + b_ih0, HMMA bf16 3-split. (proven)
// Block 0 zeroes the scan's progress flags (runs before scan launches).
// ===========================================================================
#define ROWB 80
#define SM_BIAS 0
#define SM_AHI  512
#define SM_ALO  (512 + 20480)
#define SM_BHI  (512 + 40960)
#define SM_BLO  (512 + 40960 + 7680)
#define GEMM_SMEM (512 + 40960 + 15360)   // 56832 bytes

__global__ __launch_bounds__(256, 1) void xproj_gemm(const float* __restrict__ X,
                                                     const float* __restrict__ W,
                                                     const float* __restrict__ bias)
{
    extern __shared__ char smem[];
    float* sbias = (float*)(smem + SM_BIAS);
    const int tid = threadIdx.x, lane = tid & 31, warp = tid >> 5;
    const int rowbase = blockIdx.x * 256;
    const int m_warp = (warp & 3) * 64;
    const int n_warp = (warp >> 2) * 48;

    if (blockIdx.x == 0 && tid < 2 * B_DIM) g_prog[tid] = 0;
    if (tid < H_DIM) sbias[tid] = __ldg(bias + tid);

    const int g = lane >> 3, r = lane & 7;
    const uint32_t lane_off = (uint32_t)((((g & 1) << 3) + r) * ROWB + ((g >> 1) << 4));
    const uint32_t sb = smem_u32(smem);
    const uint32_t aHiB = sb + SM_AHI + (uint32_t)m_warp * ROWB + lane_off;
    const uint32_t aLoB = sb + SM_ALO + (uint32_t)m_warp * ROWB + lane_off;
    const uint32_t bHiB = sb + SM_BHI + (uint32_t)n_warp * ROWB + lane_off;
    const uint32_t bLoB = sb + SM_BLO + (uint32_t)n_warp * ROWB + lane_off;

    float acc[4][6][4];
    #pragma unroll
    for (int mt = 0; mt < 4; mt++)
        #pragma unroll
        for (int nt = 0; nt < 6; nt++)
            #pragma unroll
            for (int i = 0; i < 4; i++) acc[mt][nt][i] = 0.f;

    float4 sa[8], sw[3];

    auto load_stage = [&](int k0) {
        #pragma unroll
        for (int it = 0; it < 8; ++it) {
            int f = tid + it * 256;
            sa[it] = *(const float4*)(X + (size_t)(rowbase + (f >> 3)) * I_DIM + k0 + ((f & 7) << 2));
        }
        #pragma unroll
        for (int it = 0; it < 3; ++it) {
            int f = tid + it * 256;
            sw[it] = *(const float4*)(W + (size_t)(f >> 3) * I_DIM + k0 + ((f & 7) << 2));
        }
    };
    auto store_stage = [&]() {
        #pragma unroll
        for (int it = 0; it < 8; ++it) {
            int f = tid + it * 256;
            int off = (f >> 3) * ROWB + ((f & 7) << 3);
            uint2 hp, lp; cvt_hilo(sa[it], hp, lp);
            *(uint2*)(smem + SM_AHI + off) = hp;
            *(uint2*)(smem + SM_ALO + off) = lp;
        }
        #pragma unroll
        for (int it = 0; it < 3; ++it) {
            int f = tid + it * 256;
            int off = (f >> 3) * ROWB + ((f & 7) << 3);
            uint2 hp, lp; cvt_hilo(sw[it], hp, lp);
            *(uint2*)(smem + SM_BHI + off) = hp;
            *(uint2*)(smem + SM_BLO + off) = lp;
        }
    };

    load_stage(0);
    store_stage();
    __syncthreads();

    const int NC = I_DIM / 32;   // 64
    for (int c = 0; c < NC; ++c) {
        if (c + 1 < NC) load_stage((c + 1) * 32);

        #pragma unroll
        for (int s = 0; s < 2; ++s) {
            uint32_t ah[4][4], al[4][4], bh[6][2], bl[6][2];
            #pragma unroll
            for (int mt = 0; mt < 4; ++mt) {
                ldsm_x4(ah[mt][0], ah[mt][1], ah[mt][2], ah[mt][3], aHiB + mt * (16 * ROWB) + s * 32);
                ldsm_x4(al[mt][0], al[mt][1], al[mt][2], al[mt][3], aLoB + mt * (16 * ROWB) + s * 32);
            }
            #pragma unroll
            for (int np = 0; np < 3; ++np) {
                uint32_t r0, r1, r2, r3;
                ldsm_x4(r0, r1, r2, r3, bHiB + np * (16 * ROWB) + s * 32);
                bh[2 * np][0] = r0; bh[2 * np + 1][0] = r1;
                bh[2 * np][1] = r2; bh[2 * np + 1][1] = r3;
                ldsm_x4(r0, r1, r2, r3, bLoB + np * (16 * ROWB) + s * 32);
                bl[2 * np][0] = r0; bl[2 * np + 1][0] = r1;
                bl[2 * np][1] = r2; bl[2 * np + 1][1] = r3;
            }
            #pragma unroll
            for (int mt = 0; mt < 4; ++mt)
                #pragma unroll
                for (int nt = 0; nt < 6; ++nt) {
                    mma16816(acc[mt][nt], ah[mt], bh[nt]);
                    mma16816(acc[mt][nt], ah[mt], bl[nt]);
                    mma16816(acc[mt][nt], al[mt], bh[nt]);
                }
        }
        __syncthreads();
        if (c + 1 < NC) { store_stage(); }
        __syncthreads();
    }

    #pragma unroll
    for (int nt = 0; nt < 6; ++nt) {
        int col = n_warp + nt * 8 + (lane & 3) * 2;
        float b0 = sbias[col], b1 = sbias[col + 1];
        #pragma unroll
        for (int mt = 0; mt < 4; ++mt) {
            int row0 = rowbase + m_warp + mt * 16 + (lane >> 2);
            float2 v0 = make_float2(acc[mt][nt][0] + b0, acc[mt][nt][1] + b1);
            float2 v1 = make_float2(acc[mt][nt][2] + b0, acc[mt][nt][3] + b1);
            *(float2*)(g_xproj + (size_t)row0 * H_DIM + col) = v0;
            *(float2*)(g_xproj + (size_t)(row0 + 8) * H_DIM + col) = v1;
        }
    }
}

// ===========================================================================
// Kernel 2: scan. One CTA per (batch, layer); 192 thr:
//  R group (tid 0-95): output j. FULL whh row j in regs. Per step: broadcast
//    LDS h -> 48 fma2 (4 chains) -> tanh(+u) -> STS h. No shfl, no global ops.
//  P group (tid 96-191): everything latency-tolerant: u(v)=wih*x_v+biases
//    computed 2 steps ahead into a 4-slot smem ring; input stream staged via
//    flag-gated LDG (8-step cadence, warmup lag 32); h copied to the output
//    stream one step late; flags published every 8 steps.
// One CTA-wide __syncthreads per step. Producers never wait on consumers.
// ===========================================================================
#define ST_OFF 0                         // stage ring: 16 x 96 floats (l1/2)
#define U_OFF  6144                      // u ring: 4 x 96
#define H_OFF  7680                      // h: 2 x 96
#define SR_OFF 8448                      // reduce: 96
#define SCAN_SMEM 8832

__global__ __launch_bounds__(192, 2) void rnn_layer(
    const float* __restrict__ whh0, const float* __restrict__ bhh0,
    const float* __restrict__ wih1, const float* __restrict__ whh1,
    const float* __restrict__ bih1, const float* __restrict__ bhh1,
    const float* __restrict__ wih2, const float* __restrict__ whh2,
    const float* __restrict__ bih2, const float* __restrict__ bhh2,
    const float* __restrict__ fcw,  const float* __restrict__ fcb,
    float* __restrict__ out)
{
    __shared__ __align__(16) char smbuf[SCAN_SMEM];

    const int layer = blockIdx.x >> 6;
    const int b     = blockIdx.x & 63;
    const int tid   = threadIdx.x;

    const uint32_t stb = smem_u32(smbuf) + ST_OFF;
    const uint32_t ub  = smem_u32(smbuf) + U_OFF;
    const uint32_t hb  = smem_u32(smbuf) + H_OFF;

    sts_f32(hb + tid * 4, 0.f);           // zero h (both parities, 192 floats)

    const size_t soff = (size_t)b * T_DIM * H_DIM;

    if (layer == 0) {
        // ============================ LAYER 0 ============================
        float* outstream = g_h0 + soff;
        int*   outflag   = &g_prog[b];

        if (tid < 96) {
            const int j = tid;
            ull w[48];
            {
                const float* wr = whh0 + j * H_DIM;
                #pragma unroll
                for (int q = 0; q < 48; q++) w[q] = pack2(__ldg(wr + 2 * q), __ldg(wr + 2 * q + 1));
            }
            const float bias = __ldg(bhh0 + j);
            const float* xpp = g_xproj + soff + j;
            float xc[8], xn[8];
            #pragma unroll
            for (int r = 0; r < 8; r++) xc[r] = __ldg(xpp + (size_t)r * H_DIM);
            #pragma unroll
            for (int r = 0; r < 8; r++) xn[r] = __ldg(xpp + (size_t)(8 + r) * H_DIM);
            __syncthreads();

            const uint32_t dst_j = hb + (uint32_t)(j * 4);
            for (int ow = 0; ow < 64; ++ow) {
                #pragma unroll
                for (int si = 0; si < 8; ++si) {
                    const uint32_t src = hb + (uint32_t)(((si & 1) ^ 1) * 384);
                    float d = dot96(src, w);
                    float hv = fast_tanh(d + xc[si] + bias);
                    sts_f32(dst_j + (uint32_t)((si & 1) * 384), hv);
                    __syncthreads();
                }
                #pragma unroll
                for (int r = 0; r < 8; r++) xc[r] = xn[r];
                #pragma unroll
                for (int r = 0; r < 8; r++) {
                    int t = 8 * ow + 16 + r; if (t > T_DIM - 1) t = T_DIM - 1;
                    xn[r] = __ldg(xpp + (size_t)t * H_DIM);
                }
            }
        } else {
            const int jj = tid - 96;
            __syncthreads();
            for (int ow = 0; ow < 64; ++ow) {
                #pragma unroll
                for (int si = 0; si < 8; ++si) {
                    const int w = 8 * ow + si;
                    if (si == 1 && ow >= 1 && tid == 96) stg_rel(outflag, w - 1);
                    if (w >= 1) {
                        float hv = lds_f32(hb + (uint32_t)((((si & 1) ^ 1)) * 384 + jj * 4));
                        outstream[(size_t)(w - 1) * H_DIM + jj] = hv;
                    }
                    __syncthreads();
                }
            }
        }
        // drain: copy h(511), publish final flag
        __syncthreads();
        if (tid >= 96) {
            const int jj = tid - 96;
            outstream[(size_t)(T_DIM - 1) * H_DIM + jj] = lds_f32(hb + (uint32_t)(384 + jj * 4));
        }
        __syncthreads();
        if (tid == 96) stg_rel(outflag, T_DIM);
    } else {
        // ========================== LAYER 1 / 2 ==========================
        const float* instream  = (layer == 1) ? (g_h0 + soff) : (g_h1 + soff);
        float*       outstream = (layer == 1) ? (g_h1 + soff) : nullptr;
        const int*   inflag    = (layer == 1) ? &g_prog[b] : &g_prog[64 + b];
        int*         outflag   = (layer == 1) ? &g_prog[64 + b] : nullptr;

        if (tid < 96) {
            const int j = tid;
            ull w[48];
            {
                const float* wr = ((layer == 1) ? whh1 : whh2) + j * H_DIM;
                #pragma unroll
                for (int q = 0; q < 48; q++) w[q] = pack2(__ldg(wr + 2 * q), __ldg(wr + 2 * q + 1));
            }
            __syncthreads();   // (1) stage filled
            __syncthreads();   // (2) u(0), u(1) ready

            const uint32_t dst_j = hb + (uint32_t)(j * 4);
            const uint32_t uj    = ub + (uint32_t)(j * 4);
            for (int ow = 0; ow < 64; ++ow) {
                #pragma unroll
                for (int si = 0; si < 8; ++si) {
                    const uint32_t src = hb + (uint32_t)(((si & 1) ^ 1) * 384);
                    float d = dot96(src, w);
                    float uval = lds_f32(uj + (uint32_t)((si & 3) * 384));
                    float hv = fast_tanh(d + uval);
                    sts_f32(dst_j + (uint32_t)((si & 1) * 384), hv);
                    __syncthreads();
                }
            }
        } else {
            const int jj = tid - 96;
            ull w[48];
            {
                const float* wr = ((layer == 1) ? wih1 : wih2) + jj * H_DIM;
                #pragma unroll
                for (int q = 0; q < 48; q++) w[q] = pack2(__ldg(wr + 2 * q), __ldg(wr + 2 * q + 1));
            }
            const float biass = (layer == 1)
                ? (__ldg(bih1 + jj) + __ldg(bhh1 + jj))
                : (__ldg(bih2 + jj) + __ldg(bhh2 + jj));

            // warmup: stage rows 0..15, lr rows 16..23
            float lr[8];
            GPOLL(inflag, 32);
            #pragma unroll
            for (int r = 0; r < 16; r++)
                sts_f32(stb + (uint32_t)(r * 384 + jj * 4), instream[(size_t)r * H_DIM + jj]);
            #pragma unroll
            for (int r = 0; r < 8; r++) lr[r] = instream[(size_t)(16 + r) * H_DIM + jj];
            __syncthreads();   // (1) stage visible
            // u(0), u(1)
            #pragma unroll
            for (int v = 0; v < 2; v++) {
                float d = dot96(stb + (uint32_t)(v * 384), w);
                sts_f32(ub + (uint32_t)(v * 384 + jj * 4), d + biass);
            }
            __syncthreads();   // (2) u ready

            const uint32_t ujj = ub + (uint32_t)(jj * 4);
            for (int ow = 0; ow < 64; ++ow) {
                #pragma unroll
                for (int si = 0; si < 8; ++si) {
                    const int w_ = 8 * ow + si;
                    if (layer == 1 && si == 1 && ow >= 1 && tid == 96) stg_rel(outflag, w_ - 1);
                    if (si == 0 && ow >= 1) {
                        if (w_ + 8 < T_DIM) {
                            #pragma unroll
                            for (int r = 0; r < 8; r++)
                                sts_f32(stb + (uint32_t)((((w_ + 8 + r) & 15)) * 384 + jj * 4), lr[r]);
                        }
                        if (w_ + 16 < T_DIM) {
                            int need = w_ + 24; if (need > T_DIM) need = T_DIM;
                            GPOLL(inflag, need);
                            #pragma unroll
                            for (int r = 0; r < 8; r++)
                                lr[r] = instream[(size_t)(w_ + 16 + r) * H_DIM + jj];
                        }
                    }
                    if (w_ + 2 < T_DIM) {
                        float d = dot96(stb + (uint32_t)(((w_ + 2) & 15) * 384), w);
                        sts_f32(ujj + (uint32_t)(((si + 2) & 3) * 384), d + biass);
                    }
                    if (layer == 1 && w_ >= 1) {
                        float hv = lds_f32(hb + (uint32_t)((((si & 1) ^ 1)) * 384 + jj * 4));
                        outstream[(size_t)(w_ - 1) * H_DIM + jj] = hv;
                    }
                    __syncthreads();
                }
            }
        }

        if (layer == 1) {
            __syncthreads();
            if (tid >= 96) {
                const int jj = tid - 96;
                outstream[(size_t)(T_DIM - 1) * H_DIM + jj] = lds_f32(hb + (uint32_t)(384 + jj * 4));
            }
            __syncthreads();
            if (tid == 96) stg_rel(outflag, T_DIM);
        } else {
            // FC head: out[b] = h2[511] . fc_w + fc_b   (parity 1)
            const uint32_t srb = smem_u32(smbuf) + SR_OFF;
            if (tid < 96)
                sts_f32(srb + tid * 4, lds_f32(hb + (uint32_t)(384 + tid * 4)) * __ldg(fcw + tid));
            __syncthreads();
            if (tid == 0) {
                float s = __ldg(fcb);
                #pragma unroll
                for (int k = 0; k < H_DIM; k++) s += lds_f32(srb + k * 4);
                out[b] = s;
            }
        }
    }
}

extern "C" void kernel_launch(void* const* d_in, const int* in_sizes, int n_in,
                              void* d_out, int out_size) {
    const float* x     = (const float*)d_in[0];
    const float* w_ih0 = (const float*)d_in[1];
    const float* w_hh0 = (const float*)d_in[2];
    const float* b_ih0 = (const float*)d_in[3];
    const float* b_hh0 = (const float*)d_in[4];
    const float* w_ih1 = (const float*)d_in[5];
    const float* w_hh1 = (const float*)d_in[6];
    const float* b_ih1 = (const float*)d_in[7];
    const float* b_hh1 = (const float*)d_in[8];
    const float* w_ih2 = (const float*)d_in[9];
    const float* w_hh2 = (const float*)d_in[10];
    const float* b_ih2 = (const float*)d_in[11];
    const float* b_hh2 = (const float*)d_in[12];
    const float* fc_w  = (const float*)d_in[13];
    const float* fc_b  = (const float*)d_in[14];
    float* out = (float*)d_out;

    cudaFuncSetAttribute(xproj_gemm, cudaFuncAttributeMaxDynamicSharedMemorySize, GEMM_SMEM);
    xproj_gemm<<<(B_DIM * T_DIM) / 256, 256, GEMM_SMEM>>>(x, w_ih0, b_ih0);
    rnn_layer<<<3 * B_DIM, 192>>>(w_hh0, b_hh0,
                                  w_ih1, w_hh1, b_ih1, b_hh1,
                                  w_ih2, w_hh2, b_ih2, b_hh2,
                                  fc_w, fc_b, out);
}

// round 10
// speedup vs baseline: 1.5241x; 1.0528x over previous
#include <cuda_runtime.h>
#include <cuda_bf16.h>
#include <cstdint>

#define I_DIM 2048
#define H_DIM 96
#define B_DIM 64
#define T_DIM 512

typedef unsigned long long ull;

// ============================ generic helpers ==============================

__device__ __forceinline__ void fma2(ull &d, ull a, ull b) {
    asm("fma.rn.f32x2 %0, %1, %2, %0;" : "+l"(d) : "l"(a), "l"(b));
}
__device__ __forceinline__ ull pack2(float lo, float hi) {
    ull v; asm("mov.b64 %0, {%1, %2};" : "=l"(v) : "f"(lo), "f"(hi)); return v;
}
__device__ __forceinline__ float fast_tanh(float x) {
    float e = __expf(2.0f * x);
    return 1.0f - __fdividef(2.0f, e + 1.0f);
}
__device__ __forceinline__ uint32_t smem_u32(const void* p) {
    uint32_t a;
    asm("{ .reg .u64 t; cvta.to.shared.u64 t, %1; cvt.u32.u64 %0, t; }" : "=r"(a) : "l"(p));
    return a;
}
__device__ __forceinline__ void lds_v2u64(ull &x, ull &y, uint32_t a) {
    asm volatile("ld.shared.v2.b64 {%0,%1}, [%2];" : "=l"(x), "=l"(y) : "r"(a));
}
__device__ __forceinline__ void sts_f32(uint32_t a, float v) {
    asm volatile("st.shared.f32 [%0], %1;" :: "r"(a), "f"(v) : "memory");
}
__device__ __forceinline__ void sts_u16(uint32_t a, uint16_t v) {
    asm volatile("st.shared.u16 [%0], %1;" :: "r"(a), "h"(v) : "memory");
}
__device__ __forceinline__ float lds_f32(uint32_t a) {
    float v; asm volatile("ld.shared.f32 %0, [%1];" : "=f"(v) : "r"(a)); return v;
}
__device__ __forceinline__ float hsum4x(ull a0, ull a1, ull a2, ull a3) {
    ull t, u, v;
    asm("add.rn.f32x2 %0, %1, %2;" : "=l"(t) : "l"(a0), "l"(a1));
    asm("add.rn.f32x2 %0, %1, %2;" : "=l"(u) : "l"(a2), "l"(a3));
    asm("add.rn.f32x2 %0, %1, %2;" : "=l"(v) : "l"(t), "l"(u));
    float lo, hi; asm("mov.b64 {%0,%1}, %2;" : "=f"(lo), "=f"(hi) : "l"(v));
    return lo + hi;
}
// cross-CTA progress flags (gpu scope)
__device__ __forceinline__ int ldg_acq(const int* p) {
    int v; asm volatile("ld.global.acquire.gpu.u32 %0, [%1];" : "=r"(v) : "l"(p) : "memory");
    return v;
}
__device__ __forceinline__ void stg_rel(int* p, int v) {
    asm volatile("membar.gl;" ::: "memory");
    asm volatile("st.global.release.gpu.u32 [%0], %1;" :: "l"(p), "r"(v) : "memory");
}
#define GPOLL(p, val) do { \
    if (ldg_acq(p) < (val)) { while (ldg_acq(p) < (val)) __nanosleep(64); } \
} while (0)
#define PBAR() asm volatile("bar.sync 5, 96;" ::: "memory")

// 96-float dot: broadcast LDS from src, weights in wreg[48] (ull pairs).
__device__ __forceinline__ float dot96(uint32_t src, const ull* wreg) {
    ull a0 = 0, a1 = 0, a2 = 0, a3 = 0;
    #pragma unroll
    for (int k = 0; k < 24; k++) {
        ull vx, vy; lds_v2u64(vx, vy, src + 16 * k);
        if (k & 1) { fma2(a2, wreg[2 * k], vx); fma2(a3, wreg[2 * k + 1], vy); }
        else       { fma2(a0, wreg[2 * k], vx); fma2(a1, wreg[2 * k + 1], vy); }
    }
    return hsum4x(a0, a1, a2, a3);
}

// ======================= mma.sync / ldmatrix helpers =======================

__device__ __forceinline__ void ldsm_x4(uint32_t &r0, uint32_t &r1, uint32_t &r2,
                                        uint32_t &r3, uint32_t addr) {
    asm volatile("ldmatrix.sync.aligned.m8n8.x4.shared.b16 {%0,%1,%2,%3}, [%4];"
                 : "=r"(r0), "=r"(r1), "=r"(r2), "=r"(r3) : "r"(addr));
}
__device__ __forceinline__ void ldsm_x2(uint32_t &r0, uint32_t &r1, uint32_t addr) {
    asm volatile("ldmatrix.sync.aligned.m8n8.x2.shared.b16 {%0,%1}, [%2];"
                 : "=r"(r0), "=r"(r1) : "r"(addr));
}
__device__ __forceinline__ void mma16816(float* c, const uint32_t* a, const uint32_t* b) {
    asm volatile("mma.sync.aligned.m16n8k16.row.col.f32.bf16.bf16.f32 "
                 "{%0,%1,%2,%3}, {%4,%5,%6,%7}, {%8,%9}, {%0,%1,%2,%3};"
                 : "+f"(c[0]), "+f"(c[1]), "+f"(c[2]), "+f"(c[3])
                 : "r"(a[0]), "r"(a[1]), "r"(a[2]), "r"(a[3]), "r"(b[0]), "r"(b[1]));
}
__device__ __forceinline__ void cvt_hilo(float4 v, uint2 &hp, uint2 &lp) {
    __nv_bfloat162 h0 = __float22bfloat162_rn(make_float2(v.x, v.y));
    __nv_bfloat162 h1 = __float22bfloat162_rn(make_float2(v.z, v.w));
    float2 f0 = __bfloat1622float2(h0), f1 = __bfloat1622float2(h1);
    __nv_bfloat162 l0 = __float22bfloat162_rn(make_float2(v.x - f0.x, v.y - f0.y));
    __nv_bfloat162 l1 = __float22bfloat162_rn(make_float2(v.z - f1.x, v.w - f1.y));
    hp = make_uint2(*(uint32_t*)&h0, *(uint32_t*)&h1);
    lp = make_uint2(*(uint32_t*)&l0, *(uint32_t*)&l1);
}
__device__ __forceinline__ void cvt_hilo2(float2 v, uint32_t &hp, uint32_t &lp) {
    __nv_bfloat162 h = __float22bfloat162_rn(v);
    float2 f = __bfloat1622float2(h);
    __nv_bfloat162 l = __float22bfloat162_rn(make_float2(v.x - f.x, v.y - f.y));
    hp = *(uint32_t*)&h; lp = *(uint32_t*)&l;
}
__device__ __forceinline__ void cvt_hilo1(float v, uint16_t &hb, uint16_t &lb) {
    __nv_bfloat16 h = __float2bfloat16(v);
    float f = __bfloat162float(h);
    __nv_bfloat16 l = __float2bfloat16(v - f);
    hb = *(uint16_t*)&h; lb = *(uint16_t*)&l;
}

// ===================== global scratch (no allocations) =====================
__device__ float g_xproj[(size_t)B_DIM * T_DIM * H_DIM];
__device__ float g_h0[(size_t)B_DIM * T_DIM * H_DIM];
__device__ float g_h1[(size_t)B_DIM * T_DIM * H_DIM];
__device__ int   g_prog[2 * B_DIM];   // [0..63]: l0 progress, [64..127]: l1

// ===========================================================================
// Kernel 1: xproj = x @ w_ih0^T + b_ih0, HMMA bf16 3-split. (proven)
// ===========================================================================
#define ROWB 80
#define SM_BIAS 0
#define SM_AHI  512
#define SM_ALO  (512 + 20480)
#define SM_BHI  (512 + 40960)
#define SM_BLO  (512 + 40960 + 7680)
#define GEMM_SMEM (512 + 40960 + 15360)   // 56832 bytes

__global__ __launch_bounds__(256, 1) void xproj_gemm(const float* __restrict__ X,
                                                     const float* __restrict__ W,
                                                     const float* __restrict__ bias)
{
    extern __shared__ char smem[];
    float* sbias = (float*)(smem + SM_BIAS);
    const int tid = threadIdx.x, lane = tid & 31, warp = tid >> 5;
    const int rowbase = blockIdx.x * 256;
    const int m_warp = (warp & 3) * 64;
    const int n_warp = (warp >> 2) * 48;

    if (blockIdx.x == 0 && tid < 2 * B_DIM) g_prog[tid] = 0;
    if (tid < H_DIM) sbias[tid] = __ldg(bias + tid);

    const int g = lane >> 3, r = lane & 7;
    const uint32_t lane_off = (uint32_t)((((g & 1) << 3) + r) * ROWB + ((g >> 1) << 4));
    const uint32_t sb = smem_u32(smem);
    const uint32_t aHiB = sb + SM_AHI + (uint32_t)m_warp * ROWB + lane_off;
    const uint32_t aLoB = sb + SM_ALO + (uint32_t)m_warp * ROWB + lane_off;
    const uint32_t bHiB = sb + SM_BHI + (uint32_t)n_warp * ROWB + lane_off;
    const uint32_t bLoB = sb + SM_BLO + (uint32_t)n_warp * ROWB + lane_off;

    float acc[4][6][4];
    #pragma unroll
    for (int mt = 0; mt < 4; mt++)
        #pragma unroll
        for (int nt = 0; nt < 6; nt++)
            #pragma unroll
            for (int i = 0; i < 4; i++) acc[mt][nt][i] = 0.f;

    float4 sa[8], sw[3];

    auto load_stage = [&](int k0) {
        #pragma unroll
        for (int it = 0; it < 8; ++it) {
            int f = tid + it * 256;
            sa[it] = *(const float4*)(X + (size_t)(rowbase + (f >> 3)) * I_DIM + k0 + ((f & 7) << 2));
        }
        #pragma unroll
        for (int it = 0; it < 3; ++it) {
            int f = tid + it * 256;
            sw[it] = *(const float4*)(W + (size_t)(f >> 3) * I_DIM + k0 + ((f & 7) << 2));
        }
    };
    auto store_stage = [&]() {
        #pragma unroll
        for (int it = 0; it < 8; ++it) {
            int f = tid + it * 256;
            int off = (f >> 3) * ROWB + ((f & 7) << 3);
            uint2 hp, lp; cvt_hilo(sa[it], hp, lp);
            *(uint2*)(smem + SM_AHI + off) = hp;
            *(uint2*)(smem + SM_ALO + off) = lp;
        }
        #pragma unroll
        for (int it = 0; it < 3; ++it) {
            int f = tid + it * 256;
            int off = (f >> 3) * ROWB + ((f & 7) << 3);
            uint2 hp, lp; cvt_hilo(sw[it], hp, lp);
            *(uint2*)(smem + SM_BHI + off) = hp;
            *(uint2*)(smem + SM_BLO + off) = lp;
        }
    };

    load_stage(0);
    store_stage();
    __syncthreads();

    const int NC = I_DIM / 32;   // 64
    for (int c = 0; c < NC; ++c) {
        if (c + 1 < NC) load_stage((c + 1) * 32);

        #pragma unroll
        for (int s = 0; s < 2; ++s) {
            uint32_t ah[4][4], al[4][4], bh[6][2], bl[6][2];
            #pragma unroll
            for (int mt = 0; mt < 4; ++mt) {
                ldsm_x4(ah[mt][0], ah[mt][1], ah[mt][2], ah[mt][3], aHiB + mt * (16 * ROWB) + s * 32);
                ldsm_x4(al[mt][0], al[mt][1], al[mt][2], al[mt][3], aLoB + mt * (16 * ROWB) + s * 32);
            }
            #pragma unroll
            for (int np = 0; np < 3; ++np) {
                uint32_t r0, r1, r2, r3;
                ldsm_x4(r0, r1, r2, r3, bHiB + np * (16 * ROWB) + s * 32);
                bh[2 * np][0] = r0; bh[2 * np + 1][0] = r1;
                bh[2 * np][1] = r2; bh[2 * np + 1][1] = r3;
                ldsm_x4(r0, r1, r2, r3, bLoB + np * (16 * ROWB) + s * 32);
                bl[2 * np][0] = r0; bl[2 * np + 1][0] = r1;
                bl[2 * np][1] = r2; bl[2 * np + 1][1] = r3;
            }
            #pragma unroll
            for (int mt = 0; mt < 4; ++mt)
                #pragma unroll
                for (int nt = 0; nt < 6; ++nt) {
                    mma16816(acc[mt][nt], ah[mt], bh[nt]);
                    mma16816(acc[mt][nt], ah[mt], bl[nt]);
                    mma16816(acc[mt][nt], al[mt], bh[nt]);
                }
        }
        __syncthreads();
        if (c + 1 < NC) { store_stage(); }
        __syncthreads();
    }

    #pragma unroll
    for (int nt = 0; nt < 6; ++nt) {
        int col = n_warp + nt * 8 + (lane & 3) * 2;
        float b0 = sbias[col], b1 = sbias[col + 1];
        #pragma unroll
        for (int mt = 0; mt < 4; ++mt) {
            int row0 = rowbase + m_warp + mt * 16 + (lane >> 2);
            float2 v0 = make_float2(acc[mt][nt][0] + b0, acc[mt][nt][1] + b1);
            float2 v1 = make_float2(acc[mt][nt][2] + b0, acc[mt][nt][3] + b1);
            *(float2*)(g_xproj + (size_t)row0 * H_DIM + col) = v0;
            *(float2*)(g_xproj + (size_t)(row0 + 8) * H_DIM + col) = v1;
        }
    }
}

// ===========================================================================
// Kernel 2: scan. One CTA per (batch, layer); 192 thr.
//  R (tid 0-95): serial chain only: LDS h -> dot96(whh) -> tanh(+u) -> STS h
//    (+ STG h to stream for l0/l1). One CTA barrier per step.
//  P (tid 96-191): u = Wih x x via mma.sync bf16 3-split in 8-step blocks,
//    2 windows ahead, into a 3-block u-ring (9-float rows: gcd(9,32)=1 =>
//    conflict-free R reads; scalar stores only - 36B rows are NOT 8B aligned).
//  l0's u is g_xproj (precomputed) - its P only publishes flags.
// ===========================================================================
#define UB_STRIDE 3456                 // one u block: 96 rows x 9 floats
#define BS_STRIDE 1664                 // bf16 scratch: 8 rows x 208B
__global__ __launch_bounds__(192, 2) void rnn_layer(
    const float* __restrict__ whh0, const float* __restrict__ bhh0,
    const float* __restrict__ wih1, const float* __restrict__ whh1,
    const float* __restrict__ bih1, const float* __restrict__ bhh1,
    const float* __restrict__ wih2, const float* __restrict__ whh2,
    const float* __restrict__ bih2, const float* __restrict__ bhh2,
    const float* __restrict__ fcw,  const float* __restrict__ fcb,
    float* __restrict__ out)
{
    __shared__ __align__(16) float sh_h[2][H_DIM];
    __shared__ __align__(16) float sh_u[3][UB_STRIDE / 4];
    __shared__ __align__(16) char  sh_bs[2][2 * BS_STRIDE];   // [buf][hi|lo]
    __shared__ float sh_red[H_DIM];

    const int layer = blockIdx.x >> 6;
    const int b     = blockIdx.x & 63;
    const int tid   = threadIdx.x;
    const int lane  = tid & 31;

    const uint32_t hb = smem_u32(&sh_h[0][0]);
    const uint32_t ub = smem_u32(&sh_u[0][0]);

    sts_f32(hb + tid * 4, 0.f);   // zero both h parities (192 floats)

    const size_t soff = (size_t)b * T_DIM * H_DIM;

    if (layer == 0) {
        // ============================ LAYER 0 ============================
        float* outstream = g_h0 + soff;
        int*   outflag   = &g_prog[b];

        if (tid < 96) {
            const int j = tid;
            ull w[48];
            {
                const float* wr = whh0 + j * H_DIM;
                #pragma unroll
                for (int q = 0; q < 48; q++) w[q] = pack2(__ldg(wr + 2 * q), __ldg(wr + 2 * q + 1));
            }
            const float bias = __ldg(bhh0 + j);
            const float* xpp = g_xproj + soff + j;
            float xc[8], xn[8];
            #pragma unroll
            for (int r = 0; r < 8; r++) xc[r] = __ldg(xpp + (size_t)r * H_DIM);
            #pragma unroll
            for (int r = 0; r < 8; r++) xn[r] = __ldg(xpp + (size_t)(8 + r) * H_DIM);
            __syncthreads();

            const uint32_t dst_j = hb + (uint32_t)(j * 4);
            for (int ow = 0; ow < 64; ++ow) {
                #pragma unroll
                for (int si = 0; si < 8; ++si) {
                    const int v = 8 * ow + si;
                    const uint32_t src = hb + (uint32_t)(((si & 1) ^ 1) * 384);
                    float d = dot96(src, w);
                    float hv = fast_tanh(d + xc[si] + bias);
                    sts_f32(dst_j + (uint32_t)((si & 1) * 384), hv);
                    outstream[(size_t)v * H_DIM + j] = hv;
                    __syncthreads();
                }
                #pragma unroll
                for (int r = 0; r < 8; r++) xc[r] = xn[r];
                #pragma unroll
                for (int r = 0; r < 8; r++) {
                    int t = 8 * ow + 16 + r; if (t > T_DIM - 1) t = T_DIM - 1;
                    xn[r] = __ldg(xpp + (size_t)t * H_DIM);
                }
            }
        } else {
            __syncthreads();
            for (int ow = 0; ow < 64; ++ow) {
                #pragma unroll
                for (int si = 0; si < 8; ++si) __syncthreads();
                if (tid == 96) stg_rel(outflag, 8 * ow + 8);
            }
        }
    } else {
        // ========================== LAYER 1 / 2 ==========================
        const float* instream  = (layer == 1) ? (g_h0 + soff) : (g_h1 + soff);
        float*       outstream = (layer == 1) ? (g_h1 + soff) : nullptr;
        const int*   inflag    = (layer == 1) ? &g_prog[b] : &g_prog[64 + b];
        int*         outflag   = (layer == 1) ? &g_prog[64 + b] : nullptr;

        if (tid < 96) {
            // -------- R: serial recurrence --------
            const int j = tid;
            ull w[48];
            {
                const float* wr = ((layer == 1) ? whh1 : whh2) + j * H_DIM;
                #pragma unroll
                for (int q = 0; q < 48; q++) w[q] = pack2(__ldg(wr + 2 * q), __ldg(wr + 2 * q + 1));
            }
            const float bias = (layer == 1)
                ? (__ldg(bih1 + j) + __ldg(bhh1 + j))
                : (__ldg(bih2 + j) + __ldg(bhh2 + j));
            __syncthreads();

            const uint32_t dst_j = hb + (uint32_t)(j * 4);
            for (int ow = 0; ow < 64; ++ow) {
                const uint32_t ublk = ub + (uint32_t)((ow % 3) * UB_STRIDE + j * 36);
                #pragma unroll
                for (int si = 0; si < 8; ++si) {
                    const int v = 8 * ow + si;
                    const uint32_t src = hb + (uint32_t)(((si & 1) ^ 1) * 384);
                    float d = dot96(src, w);
                    float uval = lds_f32(ublk + (uint32_t)(si * 4));
                    float hv = fast_tanh(d + uval + bias);
                    sts_f32(dst_j + (uint32_t)((si & 1) * 384), hv);
                    if (layer == 1) outstream[(size_t)v * H_DIM + j] = hv;
                    __syncthreads();
                }
            }
        } else {
            // -------- P: u-projection via tensor cores --------
            const int jj = tid - 96;
            const int wp = jj >> 5;                 // P warp 0..2: out rows 32wp..
            const float* wih = (layer == 1) ? wih1 : wih2;

            // A fragments (Wih) straight from global, bf16 hi/lo, regs.
            uint32_t aH[2][6][4], aL[2][6][4];
            {
                const int q = lane >> 2, kq = 2 * (lane & 3);
                #pragma unroll
                for (int mt = 0; mt < 2; ++mt) {
                    const int r0 = 32 * wp + 16 * mt + q;
                    #pragma unroll
                    for (int kc = 0; kc < 6; ++kc) {
                        const int k0 = 16 * kc + kq;
                        float2 v00 = *(const float2*)(wih + r0 * H_DIM + k0);
                        float2 v10 = *(const float2*)(wih + (r0 + 8) * H_DIM + k0);
                        float2 v01 = *(const float2*)(wih + r0 * H_DIM + k0 + 8);
                        float2 v11 = *(const float2*)(wih + (r0 + 8) * H_DIM + k0 + 8);
                        cvt_hilo2(v00, aH[mt][kc][0], aL[mt][kc][0]);
                        cvt_hilo2(v10, aH[mt][kc][1], aL[mt][kc][1]);
                        cvt_hilo2(v01, aH[mt][kc][2], aL[mt][kc][2]);
                        cvt_hilo2(v11, aH[mt][kc][3], aL[mt][kc][3]);
                    }
                }
            }

            const uint32_t bs0 = smem_u32(&sh_bs[0][0]);
            const uint32_t bs1 = smem_u32(&sh_bs[1][0]);
            const uint32_t bladdr = (uint32_t)((lane & 7) * 208 + ((lane >> 3) & 1) * 16);

            // pack 8 floats (steps) for column jj into scratch buf
            auto pack8 = [&](uint32_t buf, const float* v8) {
                #pragma unroll
                for (int r = 0; r < 8; r++) {
                    uint16_t hbv, lbv; cvt_hilo1(v8[r], hbv, lbv);
                    sts_u16(buf + (uint32_t)(r * 208 + jj * 2), hbv);
                    sts_u16(buf + BS_STRIDE + (uint32_t)(r * 208 + jj * 2), lbv);
                }
            };
            // mma one 8-step block from scratch buf into u block at ublk
            // (scalar stores: 36B row stride is 4-mod-8 for odd rows)
            auto mma_block = [&](uint32_t buf, uint32_t ublk) {
                float cfr[2][4] = {{0.f,0.f,0.f,0.f},{0.f,0.f,0.f,0.f}};
                #pragma unroll
                for (int kc = 0; kc < 6; ++kc) {
                    uint32_t bh[2], bl[2];
                    ldsm_x2(bh[0], bh[1], buf + bladdr + kc * 32);
                    ldsm_x2(bl[0], bl[1], buf + BS_STRIDE + bladdr + kc * 32);
                    #pragma unroll
                    for (int mt = 0; mt < 2; ++mt) {
                        mma16816(cfr[mt], aH[mt][kc], bh);
                        mma16816(cfr[mt], aH[mt][kc], bl);
                        mma16816(cfr[mt], aL[mt][kc], bh);
                    }
                }
                #pragma unroll
                for (int mt = 0; mt < 2; ++mt) {
                    const int row = 32 * wp + 16 * mt + (lane >> 2);
                    const uint32_t a0 = ublk + (uint32_t)(row * 36 + (lane & 3) * 8);
                    sts_f32(a0,           cfr[mt][0]);
                    sts_f32(a0 + 4,       cfr[mt][1]);
                    sts_f32(a0 + 8 * 36,     cfr[mt][2]);
                    sts_f32(a0 + 8 * 36 + 4, cfr[mt][3]);
                }
            };

            // warmup: blocks 0,1 + lr = steps 16..23
            float lr[8];
            GPOLL(inflag, 24);
            {
                float t8[8];
                #pragma unroll
                for (int r = 0; r < 8; r++) t8[r] = instream[(size_t)r * H_DIM + jj];
                pack8(bs0, t8);
                PBAR();
                mma_block(bs0, ub + 0 * UB_STRIDE);
                #pragma unroll
                for (int r = 0; r < 8; r++) t8[r] = instream[(size_t)(8 + r) * H_DIM + jj];
                pack8(bs1, t8);
                PBAR();
                mma_block(bs1, ub + 1 * UB_STRIDE);
                #pragma unroll
                for (int r = 0; r < 8; r++) lr[r] = instream[(size_t)(16 + r) * H_DIM + jj];
            }
            __syncthreads();

            for (int ow = 0; ow < 64; ++ow) {
                const int s0 = 8 * ow + 16;          // block ow+2 steps [s0, s0+8)
                if (s0 < T_DIM) {
                    const uint32_t buf = (ow & 1) ? bs1 : bs0;
                    pack8(buf, lr);
                    PBAR();
                    mma_block(buf, ub + (uint32_t)(((ow + 2) % 3) * UB_STRIDE));
                }
                if (8 * ow + 24 < T_DIM) {
                    int need = 8 * ow + 32; if (need > T_DIM) need = T_DIM;
                    GPOLL(inflag, need);
                    #pragma unroll
                    for (int r = 0; r < 8; r++)
                        lr[r] = instream[(size_t)(8 * ow + 24 + r) * H_DIM + jj];
                }
                #pragma unroll
                for (int si = 0; si < 8; ++si) __syncthreads();
                if (layer == 1 && tid == 96) stg_rel(outflag, 8 * ow + 8);
            }
        }

        if (layer == 2) {
            // FC head: out[b] = h2[T-1] . fc_w + fc_b  (T-1 = 511 -> parity 1)
            const uint32_t srb = smem_u32(sh_red);
            if (tid < 96)
                sts_f32(srb + tid * 4, lds_f32(hb + (uint32_t)(384 + tid * 4)) * __ldg(fcw + tid));
            __syncthreads();
            if (tid == 0) {
                float s = __ldg(fcb);
                #pragma unroll
                for (int k = 0; k < H_DIM; k++) s += lds_f32(srb + k * 4);
                out[b] = s;
            }
        }
    }
}

extern "C" void kernel_launch(void* const* d_in, const int* in_sizes, int n_in,
                              void* d_out, int out_size) {
    const float* x     = (const float*)d_in[0];
    const float* w_ih0 = (const float*)d_in[1];
    const float* w_hh0 = (const float*)d_in[2];
    const float* b_ih0 = (const float*)d_in[3];
    const float* b_hh0 = (const float*)d_in[4];
    const float* w_ih1 = (const float*)d_in[5];
    const float* w_hh1 = (const float*)d_in[6];
    const float* b_ih1 = (const float*)d_in[7];
    const float* b_hh1 = (const float*)d_in[8];
    const float* w_ih2 = (const float*)d_in[9];
    const float* w_hh2 = (const float*)d_in[10];
    const float* b_ih2 = (const float*)d_in[11];
    const float* b_hh2 = (const float*)d_in[12];
    const float* fc_w  = (const float*)d_in[13];
    const float* fc_b  = (const float*)d_in[14];
    float* out = (float*)d_out;

    cudaFuncSetAttribute(xproj_gemm, cudaFuncAttributeMaxDynamicSharedMemorySize, GEMM_SMEM);
    xproj_gemm<<<(B_DIM * T_DIM) / 256, 256, GEMM_SMEM>>>(x, w_ih0, b_ih0);
    rnn_layer<<<3 * B_DIM, 192>>>(w_hh0, b_hh0,
                                  w_ih1, w_hh1, b_ih1, b_hh1,
                                  w_ih2, w_hh2, b_ih2, b_hh2,
                                  fc_w, fc_b, out);
}

// round 11
// speedup vs baseline: 1.7024x; 1.1170x over previous
#include <cuda_runtime.h>
#include <cuda_bf16.h>
#include <cstdint>

#define I_DIM 2048
#define H_DIM 96
#define B_DIM 64
#define T_DIM 512

typedef unsigned long long ull;

// ============================ generic helpers ==============================

__device__ __forceinline__ void fma2(ull &d, ull a, ull b) {
    asm("fma.rn.f32x2 %0, %1, %2, %0;" : "+l"(d) : "l"(a), "l"(b));
}
__device__ __forceinline__ ull pack2(float lo, float hi) {
    ull v; asm("mov.b64 %0, {%1, %2};" : "=l"(v) : "f"(lo), "f"(hi)); return v;
}
__device__ __forceinline__ float fast_tanh(float x) {
    float e = __expf(2.0f * x);
    return 1.0f - __fdividef(2.0f, e + 1.0f);
}
__device__ __forceinline__ uint32_t smem_u32(const void* p) {
    uint32_t a;
    asm("{ .reg .u64 t; cvta.to.shared.u64 t, %1; cvt.u32.u64 %0, t; }" : "=r"(a) : "l"(p));
    return a;
}
__device__ __forceinline__ void lds_v2u64(ull &x, ull &y, uint32_t a) {
    asm volatile("ld.shared.v2.b64 {%0,%1}, [%2];" : "=l"(x), "=l"(y) : "r"(a));
}
__device__ __forceinline__ void sts_f32(uint32_t a, float v) {
    asm volatile("st.shared.f32 [%0], %1;" :: "r"(a), "f"(v) : "memory");
}
__device__ __forceinline__ void sts_u16(uint32_t a, uint16_t v) {
    asm volatile("st.shared.u16 [%0], %1;" :: "r"(a), "h"(v) : "memory");
}
__device__ __forceinline__ float lds_f32(uint32_t a) {
    float v; asm volatile("ld.shared.f32 %0, [%1];" : "=f"(v) : "r"(a)); return v;
}
__device__ __forceinline__ float hsum4x(ull a0, ull a1, ull a2, ull a3) {
    ull t, u, v;
    asm("add.rn.f32x2 %0, %1, %2;" : "=l"(t) : "l"(a0), "l"(a1));
    asm("add.rn.f32x2 %0, %1, %2;" : "=l"(u) : "l"(a2), "l"(a3));
    asm("add.rn.f32x2 %0, %1, %2;" : "=l"(v) : "l"(t), "l"(u));
    float lo, hi; asm("mov.b64 {%0,%1}, %2;" : "=f"(lo), "=f"(hi) : "l"(v));
    return lo + hi;
}
// cross-CTA flags (gpu scope)
__device__ __forceinline__ int ldg_acq(const int* p) {
    int v; asm volatile("ld.global.acquire.gpu.u32 %0, [%1];" : "=r"(v) : "l"(p) : "memory");
    return v;
}
__device__ __forceinline__ void stg_rel(int* p, int v) {
    asm volatile("membar.gl;" ::: "memory");
    asm volatile("st.global.release.gpu.u32 [%0], %1;" :: "l"(p), "r"(v) : "memory");
}
#define GPOLL(p, val) do { \
    if (ldg_acq(p) < (val)) { while (ldg_acq(p) < (val)) __nanosleep(64); } \
} while (0)
// intra-CTA flags (smem, cta scope)
__device__ __forceinline__ int lds_acq_cta(uint32_t a) {
    int v; asm volatile("ld.acquire.cta.shared.u32 %0, [%1];" : "=r"(v) : "r"(a) : "memory");
    return v;
}
__device__ __forceinline__ void sts_rel_cta(uint32_t a, int v) {
    asm volatile("st.release.cta.shared.u32 [%0], %1;" :: "r"(a), "r"(v) : "memory");
}
#define SSPIN(addr, val) do { \
    if (lds_acq_cta(addr) < (val)) { while (lds_acq_cta(addr) < (val)) __nanosleep(32); } \
} while (0)

// 96-float dot: broadcast LDS from src, weights in wreg[48] (ull pairs).
__device__ __forceinline__ float dot96(uint32_t src, const ull* wreg) {
    ull a0 = 0, a1 = 0, a2 = 0, a3 = 0;
    #pragma unroll
    for (int k = 0; k < 24; k++) {
        ull vx, vy; lds_v2u64(vx, vy, src + 16 * k);
        if (k & 1) { fma2(a2, wreg[2 * k], vx); fma2(a3, wreg[2 * k + 1], vy); }
        else       { fma2(a0, wreg[2 * k], vx); fma2(a1, wreg[2 * k + 1], vy); }
    }
    return hsum4x(a0, a1, a2, a3);
}

// ======================= mma.sync / ldmatrix helpers =======================

__device__ __forceinline__ void ldsm_x4(uint32_t &r0, uint32_t &r1, uint32_t &r2,
                                        uint32_t &r3, uint32_t addr) {
    asm volatile("ldmatrix.sync.aligned.m8n8.x4.shared.b16 {%0,%1,%2,%3}, [%4];"
                 : "=r"(r0), "=r"(r1), "=r"(r2), "=r"(r3) : "r"(addr));
}
__device__ __forceinline__ void ldsm_x2(uint32_t &r0, uint32_t &r1, uint32_t addr) {
    asm volatile("ldmatrix.sync.aligned.m8n8.x2.shared.b16 {%0,%1}, [%2];"
                 : "=r"(r0), "=r"(r1) : "r"(addr));
}
__device__ __forceinline__ void mma16816(float* c, const uint32_t* a, const uint32_t* b) {
    asm volatile("mma.sync.aligned.m16n8k16.row.col.f32.bf16.bf16.f32 "
                 "{%0,%1,%2,%3}, {%4,%5,%6,%7}, {%8,%9}, {%0,%1,%2,%3};"
                 : "+f"(c[0]), "+f"(c[1]), "+f"(c[2]), "+f"(c[3])
                 : "r"(a[0]), "r"(a[1]), "r"(a[2]), "r"(a[3]), "r"(b[0]), "r"(b[1]));
}
__device__ __forceinline__ void cvt_hilo(float4 v, uint2 &hp, uint2 &lp) {
    __nv_bfloat162 h0 = __float22bfloat162_rn(make_float2(v.x, v.y));
    __nv_bfloat162 h1 = __float22bfloat162_rn(make_float2(v.z, v.w));
    float2 f0 = __bfloat1622float2(h0), f1 = __bfloat1622float2(h1);
    __nv_bfloat162 l0 = __float22bfloat162_rn(make_float2(v.x - f0.x, v.y - f0.y));
    __nv_bfloat162 l1 = __float22bfloat162_rn(make_float2(v.z - f1.x, v.w - f1.y));
    hp = make_uint2(*(uint32_t*)&h0, *(uint32_t*)&h1);
    lp = make_uint2(*(uint32_t*)&l0, *(uint32_t*)&l1);
}
__device__ __forceinline__ void cvt_hilo2(float2 v, uint32_t &hp, uint32_t &lp) {
    __nv_bfloat162 h = __float22bfloat162_rn(v);
    float2 f = __bfloat1622float2(h);
    __nv_bfloat162 l = __float22bfloat162_rn(make_float2(v.x - f.x, v.y - f.y));
    hp = *(uint32_t*)&h; lp = *(uint32_t*)&l;
}
__device__ __forceinline__ void cvt_hilo1(float v, uint16_t &hb, uint16_t &lb) {
    __nv_bfloat16 h = __float2bfloat16(v);
    float f = __bfloat162float(h);
    __nv_bfloat16 l = __float2bfloat16(v - f);
    hb = *(uint16_t*)&h; lb = *(uint16_t*)&l;
}

// P-group building blocks -----------------------------------------------------

// preload Wih fragments (bf16 hi/lo) straight from global into registers
__device__ __forceinline__ void fill_afrags(const float* wih, int wp, int lane,
                                            uint32_t (&aH)[2][6][4], uint32_t (&aL)[2][6][4]) {
    const int q = lane >> 2, kq = 2 * (lane & 3);
    #pragma unroll
    for (int mt = 0; mt < 2; ++mt) {
        const int r0 = 32 * wp + 16 * mt + q;
        #pragma unroll
        for (int kc = 0; kc < 6; ++kc) {
            const int k0 = 16 * kc + kq;
            float2 v00 = *(const float2*)(wih + r0 * H_DIM + k0);
            float2 v10 = *(const float2*)(wih + (r0 + 8) * H_DIM + k0);
            float2 v01 = *(const float2*)(wih + r0 * H_DIM + k0 + 8);
            float2 v11 = *(const float2*)(wih + (r0 + 8) * H_DIM + k0 + 8);
            cvt_hilo2(v00, aH[mt][kc][0], aL[mt][kc][0]);
            cvt_hilo2(v10, aH[mt][kc][1], aL[mt][kc][1]);
            cvt_hilo2(v01, aH[mt][kc][2], aL[mt][kc][2]);
            cvt_hilo2(v11, aH[mt][kc][3], aL[mt][kc][3]);
        }
    }
}
// pack 8 step-values for column jj into bf16 hi/lo scratch
__device__ __forceinline__ void pack8(uint32_t buf, int jj, const float* v8) {
    #pragma unroll
    for (int r = 0; r < 8; r++) {
        uint16_t hbv, lbv; cvt_hilo1(v8[r], hbv, lbv);
        sts_u16(buf + (uint32_t)(r * 208 + jj * 2), hbv);
        sts_u16(buf + 1664 + (uint32_t)(r * 208 + jj * 2), lbv);
    }
}
template<int KC0, int KC1>
__device__ __forceinline__ void mma_part(float (&cfr)[2][4], uint32_t buf, uint32_t bladdr,
                                         const uint32_t (&aH)[2][6][4],
                                         const uint32_t (&aL)[2][6][4]) {
    #pragma unroll
    for (int kc = KC0; kc < KC1; ++kc) {
        uint32_t bh[2], bl[2];
        ldsm_x2(bh[0], bh[1], buf + bladdr + kc * 32);
        ldsm_x2(bl[0], bl[1], buf + 1664 + bladdr + kc * 32);
        #pragma unroll
        for (int mt = 0; mt < 2; ++mt) {
            mma16816(cfr[mt], aH[mt][kc], bh);
            mma16816(cfr[mt], aH[mt][kc], bl);
            mma16816(cfr[mt], aL[mt][kc], bh);
        }
    }
}
// scalar stores: 36B row stride is 4-mod-8 on odd rows
__device__ __forceinline__ void store_cfr(const float (&cfr)[2][4], uint32_t ublk,
                                          int wp, int lane) {
    #pragma unroll
    for (int mt = 0; mt < 2; ++mt) {
        const int row = 32 * wp + 16 * mt + (lane >> 2);
        const uint32_t a0 = ublk + (uint32_t)(row * 36 + (lane & 3) * 8);
        sts_f32(a0, cfr[mt][0]);
        sts_f32(a0 + 4, cfr[mt][1]);
        sts_f32(a0 + 288, cfr[mt][2]);
        sts_f32(a0 + 292, cfr[mt][3]);
    }
}

// ===================== global scratch (no allocations) =====================
__device__ float g_xproj[(size_t)B_DIM * T_DIM * H_DIM];
__device__ float g_h0[(size_t)B_DIM * T_DIM * H_DIM];
__device__ int   g_prog[2 * B_DIM];

// ===========================================================================
// Kernel 1: xproj = x @ w_ih0^T + b_ih0, HMMA bf16 3-split. (proven)
// ===========================================================================
#define ROWB 80
#define SM_BIAS 0
#define SM_AHI  512
#define SM_ALO  (512 + 20480)
#define SM_BHI  (512 + 40960)
#define SM_BLO  (512 + 40960 + 7680)
#define GEMM_SMEM (512 + 40960 + 15360)   // 56832 bytes

__global__ __launch_bounds__(256, 1) void xproj_gemm(const float* __restrict__ X,
                                                     const float* __restrict__ W,
                                                     const float* __restrict__ bias)
{
    extern __shared__ char smem[];
    float* sbias = (float*)(smem + SM_BIAS);
    const int tid = threadIdx.x, lane = tid & 31, warp = tid >> 5;
    const int rowbase = blockIdx.x * 256;
    const int m_warp = (warp & 3) * 64;
    const int n_warp = (warp >> 2) * 48;

    if (blockIdx.x == 0 && tid < 2 * B_DIM) g_prog[tid] = 0;
    if (tid < H_DIM) sbias[tid] = __ldg(bias + tid);

    const int g = lane >> 3, r = lane & 7;
    const uint32_t lane_off = (uint32_t)((((g & 1) << 3) + r) * ROWB + ((g >> 1) << 4));
    const uint32_t sb = smem_u32(smem);
    const uint32_t aHiB = sb + SM_AHI + (uint32_t)m_warp * ROWB + lane_off;
    const uint32_t aLoB = sb + SM_ALO + (uint32_t)m_warp * ROWB + lane_off;
    const uint32_t bHiB = sb + SM_BHI + (uint32_t)n_warp * ROWB + lane_off;
    const uint32_t bLoB = sb + SM_BLO + (uint32_t)n_warp * ROWB + lane_off;

    float acc[4][6][4];
    #pragma unroll
    for (int mt = 0; mt < 4; mt++)
        #pragma unroll
        for (int nt = 0; nt < 6; nt++)
            #pragma unroll
            for (int i = 0; i < 4; i++) acc[mt][nt][i] = 0.f;

    float4 sa[8], sw[3];

    auto load_stage = [&](int k0) {
        #pragma unroll
        for (int it = 0; it < 8; ++it) {
            int f = tid + it * 256;
            sa[it] = *(const float4*)(X + (size_t)(rowbase + (f >> 3)) * I_DIM + k0 + ((f & 7) << 2));
        }
        #pragma unroll
        for (int it = 0; it < 3; ++it) {
            int f = tid + it * 256;
            sw[it] = *(const float4*)(W + (size_t)(f >> 3) * I_DIM + k0 + ((f & 7) << 2));
        }
    };
    auto store_stage = [&]() {
        #pragma unroll
        for (int it = 0; it < 8; ++it) {
            int f = tid + it * 256;
            int off = (f >> 3) * ROWB + ((f & 7) << 3);
            uint2 hp, lp; cvt_hilo(sa[it], hp, lp);
            *(uint2*)(smem + SM_AHI + off) = hp;
            *(uint2*)(smem + SM_ALO + off) = lp;
        }
        #pragma unroll
        for (int it = 0; it < 3; ++it) {
            int f = tid + it * 256;
            int off = (f >> 3) * ROWB + ((f & 7) << 3);
            uint2 hp, lp; cvt_hilo(sw[it], hp, lp);
            *(uint2*)(smem + SM_BHI + off) = hp;
            *(uint2*)(smem + SM_BLO + off) = lp;
        }
    };

    load_stage(0);
    store_stage();
    __syncthreads();

    const int NC = I_DIM / 32;   // 64
    for (int c = 0; c < NC; ++c) {
        if (c + 1 < NC) load_stage((c + 1) * 32);

        #pragma unroll
        for (int s = 0; s < 2; ++s) {
            uint32_t ah[4][4], al[4][4], bh[6][2], bl[6][2];
            #pragma unroll
            for (int mt = 0; mt < 4; ++mt) {
                ldsm_x4(ah[mt][0], ah[mt][1], ah[mt][2], ah[mt][3], aHiB + mt * (16 * ROWB) + s * 32);
                ldsm_x4(al[mt][0], al[mt][1], al[mt][2], al[mt][3], aLoB + mt * (16 * ROWB) + s * 32);
            }
            #pragma unroll
            for (int np = 0; np < 3; ++np) {
                uint32_t r0, r1, r2, r3;
                ldsm_x4(r0, r1, r2, r3, bHiB + np * (16 * ROWB) + s * 32);
                bh[2 * np][0] = r0; bh[2 * np + 1][0] = r1;
                bh[2 * np][1] = r2; bh[2 * np + 1][1] = r3;
                ldsm_x4(r0, r1, r2, r3, bLoB + np * (16 * ROWB) + s * 32);
                bl[2 * np][0] = r0; bl[2 * np + 1][0] = r1;
                bl[2 * np][1] = r2; bl[2 * np + 1][1] = r3;
            }
            #pragma unroll
            for (int mt = 0; mt < 4; ++mt)
                #pragma unroll
                for (int nt = 0; nt < 6; ++nt) {
                    mma16816(acc[mt][nt], ah[mt], bh[nt]);
                    mma16816(acc[mt][nt], ah[mt], bl[nt]);
                    mma16816(acc[mt][nt], al[mt], bh[nt]);
                }
        }
        __syncthreads();
        if (c + 1 < NC) { store_stage(); }
        __syncthreads();
    }

    #pragma unroll
    for (int nt = 0; nt < 6; ++nt) {
        int col = n_warp + nt * 8 + (lane & 3) * 2;
        float b0 = sbias[col], b1 = sbias[col + 1];
        #pragma unroll
        for (int mt = 0; mt < 4; ++mt) {
            int row0 = rowbase + m_warp + mt * 16 + (lane >> 2);
            float2 v0 = make_float2(acc[mt][nt][0] + b0, acc[mt][nt][1] + b1);
            float2 v1 = make_float2(acc[mt][nt][2] + b0, acc[mt][nt][3] + b1);
            *(float2*)(g_xproj + (size_t)row0 * H_DIM + col) = v0;
            *(float2*)(g_xproj + (size_t)(row0 + 8) * H_DIM + col) = v1;
        }
    }
}

// ===========================================================================
// Kernel 2: scan. Grid 128 (<=148 SMs: one CTA per SM).
//  Blocks 0-63:   layer 0, batch b = bid. 96 threads active (R only).
//  Blocks 64-127: layers 1+2, batch b = bid-64. 384 threads:
//    R1 (0-95)    : h1 recurrence. bar 2 with P1. h1 -> smem ring (32 slots).
//    P1 (96-191)  : u1 = Wih1 x h0-stream (global, GPOLL-gated LDG) via HMMA,
//                   work spread over 4 barrier gaps. bar 2.
//    R2 (192-287) : h2 recurrence. bar 3 with P2. FC head at end.
//    P2 (288-383) : u2 = Wih2 x h1 (smem ring; cta rel/acq counters). bar 3.
//  Ring backpressure: R1 waits p2c >= 8w-24 (satisfier always precedes waiter).
// ===========================================================================
#define L_H1   0
#define L_H2   768
#define L_RING 1536            // 32 slots x 96 floats
#define L_U1   13824           // 3 blocks x 96 x 9 floats
#define L_U2   24192
#define L_BS1  34560           // 2 bufs x (hi 1664 | lo 1664)
#define L_BS2  41216
#define L_SRED 47872
#define L_CNT  48256           // r1c @ +0, p2c @ +4
#define SCAN_SMEM 48320
#define U_STRIDE 3456

#define BAR1() asm volatile("bar.sync 1, 96;"  ::: "memory")
#define BAR2() asm volatile("bar.sync 2, 192;" ::: "memory")
#define BAR3() asm volatile("bar.sync 3, 192;" ::: "memory")
#define P1BAR() asm volatile("bar.sync 4, 96;" ::: "memory")
#define P2BAR() asm volatile("bar.sync 5, 96;" ::: "memory")

__global__ __launch_bounds__(384, 1) void rnn_layer(
    const float* __restrict__ whh0, const float* __restrict__ bhh0,
    const float* __restrict__ wih1, const float* __restrict__ whh1,
    const float* __restrict__ bih1, const float* __restrict__ bhh1,
    const float* __restrict__ wih2, const float* __restrict__ whh2,
    const float* __restrict__ bih2, const float* __restrict__ bhh2,
    const float* __restrict__ fcw,  const float* __restrict__ fcb,
    float* __restrict__ out)
{
    extern __shared__ char dyns[];
    const uint32_t dsm = smem_u32(dyns);
    const int tid = threadIdx.x;
    const int lane = tid & 31;

    if (blockIdx.x < 64) {
        // ============================ LAYER 0 ============================
        const int b = blockIdx.x;
        const size_t soff = (size_t)b * T_DIM * H_DIM;
        if (tid < 192) sts_f32(dsm + tid * 4, 0.f);      // h parity buffers
        __syncthreads();
        if (tid >= 96) return;

        const int j = tid;
        ull w[48];
        {
            const float* wr = whh0 + j * H_DIM;
            #pragma unroll
            for (int q = 0; q < 48; q++) w[q] = pack2(__ldg(wr + 2 * q), __ldg(wr + 2 * q + 1));
        }
        const float bias = __ldg(bhh0 + j);
        const float* xpp = g_xproj + soff + j;
        float* outstream = g_h0 + soff;
        int* flag = &g_prog[b];

        float xc[8], xn[8];
        #pragma unroll
        for (int r = 0; r < 8; r++) xc[r] = __ldg(xpp + (size_t)r * H_DIM);
        #pragma unroll
        for (int r = 0; r < 8; r++) xn[r] = __ldg(xpp + (size_t)(8 + r) * H_DIM);

        const uint32_t dst_j = dsm + (uint32_t)(j * 4);
        for (int ow = 0; ow < 64; ++ow) {
            #pragma unroll
            for (int si = 0; si < 8; ++si) {
                const int v = 8 * ow + si;
                float d = dot96(dsm + (uint32_t)(((si & 1) ^ 1) * 384), w);
                float hv = fast_tanh(d + xc[si] + bias);
                sts_f32(dst_j + (uint32_t)((si & 1) * 384), hv);
                outstream[(size_t)v * H_DIM + j] = hv;
                BAR1();
            }
            if (j == 0) stg_rel(flag, 8 * ow + 8);
            #pragma unroll
            for (int r = 0; r < 8; r++) xc[r] = xn[r];
            #pragma unroll
            for (int r = 0; r < 8; r++) {
                int t = 8 * ow + 16 + r; if (t > T_DIM - 1) t = T_DIM - 1;
                xn[r] = __ldg(xpp + (size_t)t * H_DIM);
            }
        }
        return;
    }

    // ============================ LAYERS 1+2 ============================
    const int b = blockIdx.x - 64;
    const size_t soff = (size_t)b * T_DIM * H_DIM;
    const uint32_t hb1 = dsm + L_H1, hb2 = dsm + L_H2, ring = dsm + L_RING;
    const uint32_t u1 = dsm + L_U1, u2 = dsm + L_U2;
    const uint32_t c_r1 = dsm + L_CNT, c_p2 = dsm + L_CNT + 4;

    if (tid < 192) { sts_f32(hb1 + tid * 4, 0.f); sts_f32(hb2 + tid * 4, 0.f); }
    if (tid == 0) { sts_f32(c_r1, 0.f); sts_f32(c_p2, 0.f); }  // bitwise zero
    __syncthreads();

    if (tid < 96) {
        // ------------------------------ R1 ------------------------------
        const int j = tid;
        ull w[48];
        {
            const float* wr = whh1 + j * H_DIM;
            #pragma unroll
            for (int q = 0; q < 48; q++) w[q] = pack2(__ldg(wr + 2 * q), __ldg(wr + 2 * q + 1));
        }
        const float bias = __ldg(bih1 + j) + __ldg(bhh1 + j);
        const uint32_t dst_j = hb1 + (uint32_t)(j * 4);
        const uint32_t ring_j = ring + (uint32_t)(j * 4);

        for (int w1 = 0; w1 < 64; ++w1) {
            SSPIN(c_p2, 8 * w1 - 24);                        // ring backpressure
            const uint32_t ublk = u1 + (uint32_t)((w1 % 3) * U_STRIDE + j * 36);
            #pragma unroll
            for (int si = 0; si < 8; ++si) {
                const int v = 8 * w1 + si;
                float uval = lds_f32(ublk + (uint32_t)(si * 4));
                float d = dot96(hb1 + (uint32_t)(((si & 1) ^ 1) * 384), w);
                float hv = fast_tanh(d + uval + bias);
                sts_f32(dst_j + (uint32_t)((si & 1) * 384), hv);
                sts_f32(ring_j + (uint32_t)((v & 31) * 384), hv);
                BAR2();
            }
            if (j == 0) sts_rel_cta(c_r1, 8 * w1 + 8);
        }
    } else if (tid < 192) {
        // ------------------------------ P1 ------------------------------
        const int jj = tid - 96;
        const int wp = jj >> 5;
        uint32_t aH[2][6][4], aL[2][6][4];
        fill_afrags(wih1, wp, lane, aH, aL);
        const uint32_t bladdr = (uint32_t)((lane & 7) * 208 + ((lane >> 3) & 1) * 16);
        const uint32_t b0 = dsm + L_BS1, b1 = dsm + L_BS1 + 3328;
        const float* instream = g_h0 + soff;
        const int* inflag = &g_prog[b];

        float lr[8], t8[8];
        GPOLL(inflag, 24);
        #pragma unroll
        for (int r = 0; r < 8; r++) t8[r] = instream[(size_t)r * H_DIM + jj];
        pack8(b0, jj, t8); P1BAR();
        { float cfr[2][4] = {{0,0,0,0},{0,0,0,0}};
          mma_part<0,6>(cfr, b0, bladdr, aH, aL);
          store_cfr(cfr, u1 + (uint32_t)(jj * 0), wp, lane); }   // block 0
        #pragma unroll
        for (int r = 0; r < 8; r++) t8[r] = instream[(size_t)(8 + r) * H_DIM + jj];
        pack8(b1, jj, t8); P1BAR();
        { float cfr[2][4] = {{0,0,0,0},{0,0,0,0}};
          mma_part<0,6>(cfr, b1, bladdr, aH, aL);
          store_cfr(cfr, u1 + U_STRIDE, wp, lane); }             // block 1
        #pragma unroll
        for (int r = 0; r < 8; r++) lr[r] = instream[(size_t)(16 + r) * H_DIM + jj];

        for (int ow = 0; ow < 64; ++ow) {
            const bool prod = (8 * ow + 16 < T_DIM);
            const uint32_t buf = (ow & 1) ? b1 : b0;
            float cfr[2][4] = {{0,0,0,0},{0,0,0,0}};
            if (prod) { pack8(buf, jj, lr); P1BAR(); mma_part<0,3>(cfr, buf, bladdr, aH, aL); }
            BAR2();
            if (prod) { mma_part<3,6>(cfr, buf, bladdr, aH, aL);
                        store_cfr(cfr, u1 + (uint32_t)(((ow + 2) % 3) * U_STRIDE), wp, lane); }
            BAR2();
            const bool fetch = (8 * ow + 24 < T_DIM);
            if (fetch) {
                int need = 8 * ow + 32; if (need > T_DIM) need = T_DIM;
                GPOLL(inflag, need);
                #pragma unroll
                for (int r = 0; r < 4; r++) lr[r] = instream[(size_t)(8 * ow + 24 + r) * H_DIM + jj];
            }
            BAR2();
            if (fetch) {
                #pragma unroll
                for (int r = 4; r < 8; r++) lr[r] = instream[(size_t)(8 * ow + 24 + r) * H_DIM + jj];
            }
            BAR2(); BAR2(); BAR2(); BAR2(); BAR2();
        }
    } else if (tid < 288) {
        // ------------------------------ R2 ------------------------------
        const int j = tid - 192;
        ull w[48];
        {
            const float* wr = whh2 + j * H_DIM;
            #pragma unroll
            for (int q = 0; q < 48; q++) w[q] = pack2(__ldg(wr + 2 * q), __ldg(wr + 2 * q + 1));
        }
        const float bias = __ldg(bih2 + j) + __ldg(bhh2 + j);
        const uint32_t dst_j = hb2 + (uint32_t)(j * 4);

        for (int w2 = 0; w2 < 64; ++w2) {
            const uint32_t ublk = u2 + (uint32_t)((w2 % 3) * U_STRIDE + j * 36);
            #pragma unroll
            for (int si = 0; si < 8; ++si) {
                float uval = lds_f32(ublk + (uint32_t)(si * 4));
                float d = dot96(hb2 + (uint32_t)(((si & 1) ^ 1) * 384), w);
                float hv = fast_tanh(d + uval + bias);
                sts_f32(dst_j + (uint32_t)((si & 1) * 384), hv);
                BAR3();
            }
        }
        // FC head: out[b] = h2[511].fc_w + fc_b (parity 1)
        sts_f32(dsm + L_SRED + (uint32_t)(j * 4),
                lds_f32(hb2 + (uint32_t)(384 + j * 4)) * __ldg(fcw + j));
        asm volatile("bar.sync 6, 96;" ::: "memory");
        if (tid == 192) {
            float s = __ldg(fcb);
            #pragma unroll
            for (int k = 0; k < H_DIM; k++) s += lds_f32(dsm + L_SRED + (uint32_t)(k * 4));
            out[b] = s;
        }
    } else {
        // ------------------------------ P2 ------------------------------
        const int jj = tid - 288;
        const int wp = jj >> 5;
        uint32_t aH[2][6][4], aL[2][6][4];
        fill_afrags(wih2, wp, lane, aH, aL);
        const uint32_t bladdr = (uint32_t)((lane & 7) * 208 + ((lane >> 3) & 1) * 16);
        const uint32_t b0 = dsm + L_BS2, b1 = dsm + L_BS2 + 3328;

        float lr[8], t8[8];
        SSPIN(c_r1, 24);
        #pragma unroll
        for (int r = 0; r < 8; r++) t8[r] = lds_f32(ring + (uint32_t)(r * 384 + jj * 4));
        pack8(b0, jj, t8); P2BAR();
        { float cfr[2][4] = {{0,0,0,0},{0,0,0,0}};
          mma_part<0,6>(cfr, b0, bladdr, aH, aL);
          store_cfr(cfr, u2, wp, lane); }
        #pragma unroll
        for (int r = 0; r < 8; r++) t8[r] = lds_f32(ring + (uint32_t)((8 + r) * 384 + jj * 4));
        pack8(b1, jj, t8); P2BAR();
        { float cfr[2][4] = {{0,0,0,0},{0,0,0,0}};
          mma_part<0,6>(cfr, b1, bladdr, aH, aL);
          store_cfr(cfr, u2 + U_STRIDE, wp, lane); }
        #pragma unroll
        for (int r = 0; r < 8; r++) lr[r] = lds_f32(ring + (uint32_t)((16 + r) * 384 + jj * 4));
        P2BAR();                                    // all P2 reads done
        if (tid == 288) sts_rel_cta(c_p2, 24);

        for (int ow = 0; ow < 64; ++ow) {
            const bool prod = (8 * ow + 16 < T_DIM);
            const uint32_t buf = (ow & 1) ? b1 : b0;
            float cfr[2][4] = {{0,0,0,0},{0,0,0,0}};
            if (prod) { pack8(buf, jj, lr); P2BAR(); mma_part<0,3>(cfr, buf, bladdr, aH, aL); }
            BAR3();
            if (prod) { mma_part<3,6>(cfr, buf, bladdr, aH, aL);
                        store_cfr(cfr, u2 + (uint32_t)(((ow + 2) % 3) * U_STRIDE), wp, lane); }
            BAR3();
            const bool fetch = (8 * ow + 24 < T_DIM);
            if (fetch) {
                int need = 8 * ow + 32; if (need > T_DIM) need = T_DIM;
                SSPIN(c_r1, need);
                #pragma unroll
                for (int r = 0; r < 8; r++)
                    lr[r] = lds_f32(ring + (uint32_t)((((8 * ow + 24 + r) & 31)) * 384 + jj * 4));
            }
            BAR3();
            if (fetch && tid == 288) sts_rel_cta(c_p2, 8 * ow + 32);
            BAR3(); BAR3(); BAR3(); BAR3(); BAR3();
        }
    }
}

extern "C" void kernel_launch(void* const* d_in, const int* in_sizes, int n_in,
                              void* d_out, int out_size) {
    const float* x     = (const float*)d_in[0];
    const float* w_ih0 = (const float*)d_in[1];
    const float* w_hh0 = (const float*)d_in[2];
    const float* b_ih0 = (const float*)d_in[3];
    const float* b_hh0 = (const float*)d_in[4];
    const float* w_ih1 = (const float*)d_in[5];
    const float* w_hh1 = (const float*)d_in[6];
    const float* b_ih1 = (const float*)d_in[7];
    const float* b_hh1 = (const float*)d_in[8];
    const float* w_ih2 = (const float*)d_in[9];
    const float* w_hh2 = (const float*)d_in[10];
    const float* b_ih2 = (const float*)d_in[11];
    const float* b_hh2 = (const float*)d_in[12];
    const float* fc_w  = (const float*)d_in[13];
    const float* fc_b  = (const float*)d_in[14];
    float* out = (float*)d_out;

    cudaFuncSetAttribute(xproj_gemm, cudaFuncAttributeMaxDynamicSharedMemorySize, GEMM_SMEM);
    cudaFuncSetAttribute(rnn_layer, cudaFuncAttributeMaxDynamicSharedMemorySize, SCAN_SMEM);
    xproj_gemm<<<(B_DIM * T_DIM) / 256, 256, GEMM_SMEM>>>(x, w_ih0, b_ih0);
    rnn_layer<<<128, 384, SCAN_SMEM>>>(w_hh0, b_hh0,
                                       w_ih1, w_hh1, b_ih1, b_hh1,
                                       w_ih2, w_hh2, b_ih2, b_hh2,
                                       fc_w, fc_b, out);
}